// round 13
// baseline (speedup 1.0000x reference)
#include <cuda_runtime.h>
#include <cuda_fp16.h>
#include <math.h>

#define BN   4
#define SEQ  1024
#define CH   768
#define NH   12
#define HD   64
#define ROWS (BN*SEQ)
#define QKVC (3*CH)
#define BH   (BN*NH)
#define BETA 0.2f
#define SCALE 0.125f
#define LN_EPS 1e-5f

__device__ __half g_xnh[(size_t)ROWS * CH];
__device__ __half g_Wh[(size_t)QKVC * CH];
__device__ __half g_qkvh[(size_t)ROWS * QKVC];
__device__ float  g_S[(size_t)BH * SEQ * SEQ];

__device__ __forceinline__ void mma16(float* c, const unsigned* a,
                                      unsigned b0, unsigned b1) {
    asm volatile(
        "mma.sync.aligned.m16n8k16.row.col.f32.f16.f16.f32 "
        "{%0,%1,%2,%3}, {%4,%5,%6,%7}, {%8,%9}, {%0,%1,%2,%3};"
        : "+f"(c[0]), "+f"(c[1]), "+f"(c[2]), "+f"(c[3])
        : "r"(a[0]), "r"(a[1]), "r"(a[2]), "r"(a[3]), "r"(b0), "r"(b1));
}

/* ================= W -> half ================= */
__global__ void wcvt_kernel(const float* __restrict__ W) {
    int i = (blockIdx.x * 256 + threadIdx.x) * 4;
    float4 v = *(const float4*)(W + i);
    __half2 h0 = __floats2half2_rn(v.x, v.y);
    __half2 h1 = __floats2half2_rn(v.z, v.w);
    uint2 u; u.x = *(unsigned*)&h0; u.y = *(unsigned*)&h1;
    *(uint2*)(g_Wh + i) = u;
}

/* ================= LayerNorm: one block per token, half out ================= */
__global__ void ln_kernel(const float* __restrict__ x,
                          const float* __restrict__ gamma,
                          const float* __restrict__ beta) {
    int row = blockIdx.x;
    const float* xr = x + (size_t)row * CH;
    __half*      orow = g_xnh + (size_t)row * CH;
    int t = threadIdx.x;

    float v0 = xr[t], v1 = xr[t + 256], v2 = xr[t + 512];
    float s  = v0 + v1 + v2;
    float sq = v0 * v0 + v1 * v1 + v2 * v2;

    __shared__ float redS[8], redQ[8], stats[2];
    #pragma unroll
    for (int o = 16; o; o >>= 1) {
        s  += __shfl_down_sync(0xffffffffu, s,  o);
        sq += __shfl_down_sync(0xffffffffu, sq, o);
    }
    int w = t >> 5, l = t & 31;
    if (l == 0) { redS[w] = s; redQ[w] = sq; }
    __syncthreads();
    if (t == 0) {
        float S = 0.f, Q = 0.f;
        #pragma unroll
        for (int i = 0; i < 8; i++) { S += redS[i]; Q += redQ[i]; }
        float mu  = S * (1.0f / CH);
        float var = Q * (1.0f / CH) - mu * mu;
        stats[0] = mu;
        stats[1] = rsqrtf(var + LN_EPS);
    }
    __syncthreads();
    float mu = stats[0], rs = stats[1];
    orow[t]       = __float2half_rn((v0 - mu) * rs * gamma[t]       + beta[t]);
    orow[t + 256] = __float2half_rn((v1 - mu) * rs * gamma[t + 256] + beta[t + 256]);
    orow[t + 512] = __float2half_rn((v2 - mu) * rs * gamma[t + 512] + beta[t + 512]);
}

/* ===== fp16 128x128 GEMM compute step (8 warps, warp 32x64) ===== */
#define COMPUTE128H(AS, BS)                                               \
    {                                                                     \
        unsigned a[2][4];                                                 \
        _Pragma("unroll")                                                 \
        for (int mi = 0; mi < 2; mi++) {                                  \
            a[mi][0] = AS[wm + mi*16 + lr    ][lc];                       \
            a[mi][1] = AS[wm + mi*16 + lr + 8][lc];                       \
            a[mi][2] = AS[wm + mi*16 + lr    ][lc + 4];                   \
            a[mi][3] = AS[wm + mi*16 + lr + 8][lc + 4];                   \
        }                                                                 \
        _Pragma("unroll")                                                 \
        for (int ni = 0; ni < 8; ni++) {                                  \
            unsigned b0 = BS[wn + ni*8 + lr][lc];                         \
            unsigned b1 = BS[wn + ni*8 + lr][lc + 4];                     \
            _Pragma("unroll")                                             \
            for (int mi = 0; mi < 2; mi++)                                \
                mma16(acc[mi][ni], a[mi], b0, b1);                        \
        }                                                                 \
    }

#define STAGE_U4(ARR, ROWI, U4OFF, v4)                                    \
    ARR[ROWI][U4OFF + 0] = v4.x; ARR[ROWI][U4OFF + 1] = v4.y;             \
    ARR[ROWI][U4OFF + 2] = v4.z; ARR[ROWI][U4OFF + 3] = v4.w;

/* ========== QKV GEMM (fp16 MMA, 128x128, double-buffered) ========== */
__global__ __launch_bounds__(256) void qkv_gemm(const float* __restrict__ bias) {
    __shared__ unsigned As[2][128][10];
    __shared__ unsigned Bs[2][128][10];
    int m0 = blockIdx.y * 128, n0 = blockIdx.x * 128;
    int t = threadIdx.x;
    int warp = t >> 5, lane = t & 31, lr = lane >> 2, lc = lane & 3;
    int wm = (warp >> 1) * 32, wn = (warp & 1) * 64;
    int sr = t >> 1, so = (t & 1) * 4;
    int sh = (t & 1) * 8;

    const __half* A0 = g_xnh + (size_t)(m0 + sr) * CH + sh;
    const __half* B0 = g_Wh  + (size_t)(n0 + sr) * CH + sh;

    float acc[2][8][4] = {};
    {
        uint4 av = *(const uint4*)A0;
        uint4 bv = *(const uint4*)B0;
        STAGE_U4(As[0], sr, so, av)
        STAGE_U4(Bs[0], sr, so, bv)
    }
    __syncthreads();

    const int NT = CH / 16;
    int buf = 0;
    for (int kt = 0; kt < NT; kt++) {
        uint4 nav, nbv;
        bool nxt = (kt + 1) < NT;
        if (nxt) {
            int k0 = (kt + 1) * 16;
            nav = *(const uint4*)(A0 + k0);
            nbv = *(const uint4*)(B0 + k0);
        }
        COMPUTE128H(As[buf], Bs[buf])
        if (nxt) {
            int nb = buf ^ 1;
            STAGE_U4(As[nb], sr, so, nav)
            STAGE_U4(Bs[nb], sr, so, nbv)
        }
        __syncthreads();
        buf ^= 1;
    }
    #pragma unroll
    for (int mi = 0; mi < 2; mi++)
        #pragma unroll
        for (int ni = 0; ni < 8; ni++) {
            int row = m0 + wm + mi*16 + lr;
            int col = n0 + wn + ni*8 + lc*2;
            float b0 = bias[col], b1 = bias[col + 1];
            __half2 h0 = __floats2half2_rn(acc[mi][ni][0] + b0, acc[mi][ni][1] + b1);
            __half2 h1 = __floats2half2_rn(acc[mi][ni][2] + b0, acc[mi][ni][3] + b1);
            *(unsigned*)(g_qkvh + (size_t)row * QKVC + col)     = *(unsigned*)&h0;
            *(unsigned*)(g_qkvh + (size_t)(row+8) * QKVC + col) = *(unsigned*)&h1;
        }
}

/* ========== Scores (fp16 MMA, 128x128, full-K staged, 1 sync) ========== */
__global__ __launch_bounds__(256) void score_gemm() {
    int bh = blockIdx.z, b = bh / NH, h = bh % NH;
    const __half* Q = g_qkvh + (size_t)b * SEQ * QKVC + h * HD;
    const __half* K = g_qkvh + (size_t)b * SEQ * QKVC + CH + h * HD;
    float* S = g_S + (size_t)bh * SEQ * SEQ;

    __shared__ unsigned As[4][128][10];
    __shared__ unsigned Bs[4][128][10];
    int m0 = blockIdx.y * 128, n0 = blockIdx.x * 128;
    int t = threadIdx.x;
    int warp = t >> 5, lane = t & 31, lr = lane >> 2, lc = lane & 3;
    int wm = (warp >> 1) * 32, wn = (warp & 1) * 64;
    int sr = t >> 1, so = (t & 1) * 4, sh = (t & 1) * 8;

    const __half* A0 = Q + (size_t)(m0 + sr) * QKVC + sh;
    const __half* B0 = K + (size_t)(n0 + sr) * QKVC + sh;

    #pragma unroll
    for (int kt = 0; kt < 4; kt++) {
        uint4 av = *(const uint4*)(A0 + kt * 16);
        uint4 bv = *(const uint4*)(B0 + kt * 16);
        STAGE_U4(As[kt], sr, so, av)
        STAGE_U4(Bs[kt], sr, so, bv)
    }
    __syncthreads();

    float acc[2][8][4] = {};
    #pragma unroll
    for (int kt = 0; kt < 4; kt++) {
        COMPUTE128H(As[kt], Bs[kt])
    }

    #pragma unroll
    for (int mi = 0; mi < 2; mi++)
        #pragma unroll
        for (int ni = 0; ni < 8; ni++) {
            int row = m0 + wm + mi*16 + lr;
            int col = n0 + wn + ni*8 + lc*2;
            float2 v0 = make_float2(acc[mi][ni][0] * SCALE, acc[mi][ni][1] * SCALE);
            float2 v1 = make_float2(acc[mi][ni][2] * SCALE, acc[mi][ni][3] * SCALE);
            *(float2*)(S + (size_t)row * SEQ + col)     = v0;
            *(float2*)(S + (size_t)(row+8) * SEQ + col) = v1;
        }
}

/* ========= Fused conv + online softmax + PV (v3, aligned) =========
   CTA = 64 query rows of one (b,h); 8 j-tiles of 128 cols.
   Sp[66][132]: cols 0..127 data (16B-aligned), 130/131 = L/R halo.
   P/V in fp16 MMA layout [8 k16-tiles][64 rows][12 uints].        */
#define BM 64
#define BJ 128
#define SP_STR 132
#define FT_SMEM ((66*SP_STR + 2*64) * 4 + 2 * (8*64*12) * 4)

__global__ __launch_bounds__(256) void fused_tail2(float* __restrict__ out) {
    int bh = blockIdx.y, b = bh / NH, h = bh % NH;
    int m0 = blockIdx.x * BM;
    const float*  Sg = g_S + (size_t)bh * SEQ * SEQ;
    const __half* Vh = g_qkvh + (size_t)b * SEQ * QKVC + 2 * CH + h * HD;

    extern __shared__ float smf[];
    float*    Sp   = smf;                              /* 66*132 */
    unsigned* Ps   = (unsigned*)(Sp + 66 * SP_STR);    /* 8*64*12 */
    unsigned* Vs   = Ps + 8 * 64 * 12;                 /* 8*64*12 */
    float*    resc = (float*)(Vs + 8 * 64 * 12);       /* 64 */
    float*    sums = resc + 64;                        /* 64 */

    int t = threadIdx.x;
    int warp = t >> 5, lane = t & 31, lr = lane >> 2, lc = lane & 3;
    int wm = (warp >> 1) * 16, wn = (warp & 1) * 32;
    int ib = t >> 2, cc = t & 3;               /* conv lanes: row, col-quarter */
    int kt2 = t >> 7, inner = t & 127;
    int kp = inner >> 4, n4 = inner & 15;      /* V staging */

    float Mi = -INFINITY, sumi = 0.f;
    float acc[4][4] = {};

    for (int jt = 0; jt < SEQ / BJ; jt++) {
        int j0 = jt * BJ;

        /* ---- stage S panel: rows m0-1..m0+64, cols j0..j0+127 ---- */
        for (int idx = t; idx < 66 * 32; idx += 256) {
            int row = idx >> 5, c4 = (idx & 31) << 2;
            int gr = m0 - 1 + row;
            float4 v = make_float4(0.f, 0.f, 0.f, 0.f);
            if (gr >= 0 && gr < SEQ)
                v = *(const float4*)(Sg + (size_t)gr * SEQ + j0 + c4);
            *(float4*)&Sp[row * SP_STR + c4] = v;
        }
        if (t < 132) {
            int row = t >> 1, side = t & 1;
            int gr = m0 - 1 + row;
            int col = side ? (j0 + BJ) : (j0 - 1);
            float v = 0.f;
            if (gr >= 0 && gr < SEQ && col >= 0 && col < SEQ)
                v = Sg[(size_t)gr * SEQ + col];
            Sp[row * SP_STR + 130 + side] = v;
        }
        /* ---- stage V (fp16, k-pair packed) ---- */
        #pragma unroll
        for (int tt = 0; tt < 4; tt++) {
            int kt = kt2 * 4 + tt;
            int krow = j0 + kt * 16 + kp * 2;
            uint2 lo = *(const uint2*)(Vh + (size_t)krow * QKVC + n4 * 4);
            uint2 hi = *(const uint2*)(Vh + (size_t)(krow + 1) * QKVC + n4 * 4);
            const __half* lp = (const __half*)&lo;
            const __half* hp = (const __half*)&hi;
            #pragma unroll
            for (int i = 0; i < 4; i++) {
                __half2 pk = __halves2half2(lp[i], hp[i]);
                Vs[(kt * 64 + n4 * 4 + i) * 12 + kp] = *(unsigned*)&pk;
            }
        }
        __syncthreads();

        /* ---- conv + online softmax ---- */
        const float* Pr0 = Sp + (size_t)ib * SP_STR;
        const float* Pr1 = Pr0 + SP_STR;
        const float* Pr2 = Pr1 + SP_STR;
        float a[32];
        float tmax = -INFINITY;
        #pragma unroll
        for (int c2 = 0; c2 < 2; c2++) {
            int B = cc * 32 + c2 * 16;
            float r0[16], r1[16], r2[16];
            #pragma unroll
            for (int x = 0; x < 4; x++) {
                *(float4*)&r0[x*4] = *(const float4*)(Pr0 + B + x*4);
                *(float4*)&r1[x*4] = *(const float4*)(Pr1 + B + x*4);
                *(float4*)&r2[x*4] = *(const float4*)(Pr2 + B + x*4);
            }
            int il = (B == 0)        ? 130 : (B - 1);
            int ir = (B + 16 == BJ)  ? 131 : (B + 16);
            float v3[18];
            v3[0]  = Pr0[il] + Pr1[il] + Pr2[il];
            v3[17] = Pr0[ir] + Pr1[ir] + Pr2[ir];
            #pragma unroll
            for (int x = 0; x < 16; x++) v3[x + 1] = r0[x] + r1[x] + r2[x];
            #pragma unroll
            for (int k = 0; k < 16; k++) {
                float av = (1.0f + BETA) * r1[k]
                         - BETA * (v3[k] + v3[k + 1] + v3[k + 2]);
                a[c2 * 16 + k] = av;
                tmax = fmaxf(tmax, av);
            }
        }
        tmax = fmaxf(tmax, __shfl_xor_sync(0xffffffffu, tmax, 1));
        tmax = fmaxf(tmax, __shfl_xor_sync(0xffffffffu, tmax, 2));
        float mnew = fmaxf(Mi, tmax);
        float scl = __expf(Mi - mnew);
        float ts = 0.f;
        unsigned pk16[16];
        #pragma unroll
        for (int k = 0; k < 32; k += 2) {
            float e0 = __expf(a[k]   - mnew);
            float e1 = __expf(a[k+1] - mnew);
            ts += e0 + e1;
            __half2 hh = __floats2half2_rn(e0, e1);
            pk16[k >> 1] = *(unsigned*)&hh;
        }
        ts += __shfl_xor_sync(0xffffffffu, ts, 1);
        ts += __shfl_xor_sync(0xffffffffu, ts, 2);
        sumi = sumi * scl + ts;
        Mi = mnew;
        if (cc == 0) {
            resc[ib] = scl;
            if (jt == SEQ / BJ - 1) sums[ib] = sumi;
        }
        #pragma unroll
        for (int c2 = 0; c2 < 2; c2++) {
            int kt = cc * 2 + c2;
            unsigned* dst = &Ps[(kt * 64 + ib) * 12];
            *(uint4*)(dst)     = make_uint4(pk16[c2*8+0], pk16[c2*8+1],
                                            pk16[c2*8+2], pk16[c2*8+3]);
            *(uint4*)(dst + 4) = make_uint4(pk16[c2*8+4], pk16[c2*8+5],
                                            pk16[c2*8+6], pk16[c2*8+7]);
        }
        __syncthreads();

        /* ---- MMA: acc = acc*rescale + P @ V ---- */
        float rs0 = resc[wm + lr], rs1 = resc[wm + lr + 8];
        #pragma unroll
        for (int ni = 0; ni < 4; ni++) {
            acc[ni][0] *= rs0; acc[ni][1] *= rs0;
            acc[ni][2] *= rs1; acc[ni][3] *= rs1;
        }
        #pragma unroll
        for (int kt = 0; kt < 8; kt++) {
            unsigned af[4];
            af[0] = Ps[(kt*64 + wm + lr    ) * 12 + lc];
            af[1] = Ps[(kt*64 + wm + lr + 8) * 12 + lc];
            af[2] = Ps[(kt*64 + wm + lr    ) * 12 + lc + 4];
            af[3] = Ps[(kt*64 + wm + lr + 8) * 12 + lc + 4];
            #pragma unroll
            for (int ni = 0; ni < 4; ni++) {
                unsigned b0 = Vs[(kt*64 + wn + ni*8 + lr) * 12 + lc];
                unsigned b1 = Vs[(kt*64 + wn + ni*8 + lr) * 12 + lc + 4];
                mma16(acc[ni], af, b0, b1);
            }
        }
        __syncthreads();
    }

    /* ---- epilogue: normalize, write ---- */
    float inv0 = 1.0f / sums[wm + lr];
    float inv1 = 1.0f / sums[wm + lr + 8];
    int r0g = m0 + wm + lr;
    #pragma unroll
    for (int ni = 0; ni < 4; ni++) {
        int col = h * HD + wn + ni * 8 + lc * 2;
        out[((size_t)b * SEQ + r0g) * CH + col    ] = acc[ni][0] * inv0;
        out[((size_t)b * SEQ + r0g) * CH + col + 1] = acc[ni][1] * inv0;
        out[((size_t)b * SEQ + r0g + 8) * CH + col    ] = acc[ni][2] * inv1;
        out[((size_t)b * SEQ + r0g + 8) * CH + col + 1] = acc[ni][3] * inv1;
    }
}

extern "C" void kernel_launch(void* const* d_in, const int* in_sizes, int n_in,
                              void* d_out, int out_size) {
    const float* x     = (const float*)d_in[0];
    const float* qkv_w = (const float*)d_in[1];
    const float* qkv_b = (const float*)d_in[2];
    const float* ln_g  = (const float*)d_in[3];
    const float* ln_b  = (const float*)d_in[4];
    float* out = (float*)d_out;

    cudaFuncSetAttribute(fused_tail2, cudaFuncAttributeMaxDynamicSharedMemorySize,
                         FT_SMEM);

    wcvt_kernel<<<(QKVC * CH) / (256 * 4), 256>>>(qkv_w);
    ln_kernel<<<ROWS, 256>>>(x, ln_g, ln_b);
    qkv_gemm<<<dim3(QKVC / 128, ROWS / 128), 256>>>(qkv_b);
    score_gemm<<<dim3(SEQ / 128, SEQ / 128, BH), 256>>>();
    fused_tail2<<<dim3(SEQ / BM, BH), 256, FT_SMEM>>>(out);
}

// round 14
// speedup vs baseline: 1.2439x; 1.2439x over previous
#include <cuda_runtime.h>
#include <cuda_fp16.h>
#include <math.h>

#define BN   4
#define SEQ  1024
#define CH   768
#define NH   12
#define HD   64
#define ROWS (BN*SEQ)
#define QKVC (3*CH)
#define BH   (BN*NH)
#define BETA 0.2f
#define SCALE 0.125f
#define LN_EPS 1e-5f

__device__ __half g_xnh[(size_t)ROWS * CH];
__device__ __half g_Wh[(size_t)QKVC * CH];
__device__ __half g_qkvh[(size_t)ROWS * QKVC];
__device__ __half g_Sh[(size_t)BH * SEQ * SEQ];
__device__ __half g_Ph[(size_t)BH * SEQ * SEQ];

__device__ __forceinline__ void mma16(float* c, const unsigned* a,
                                      unsigned b0, unsigned b1) {
    asm volatile(
        "mma.sync.aligned.m16n8k16.row.col.f32.f16.f16.f32 "
        "{%0,%1,%2,%3}, {%4,%5,%6,%7}, {%8,%9}, {%0,%1,%2,%3};"
        : "+f"(c[0]), "+f"(c[1]), "+f"(c[2]), "+f"(c[3])
        : "r"(a[0]), "r"(a[1]), "r"(a[2]), "r"(a[3]), "r"(b0), "r"(b1));
}

/* ================= W -> half ================= */
__global__ void wcvt_kernel(const float* __restrict__ W) {
    int i = (blockIdx.x * 256 + threadIdx.x) * 4;
    float4 v = *(const float4*)(W + i);
    __half2 h0 = __floats2half2_rn(v.x, v.y);
    __half2 h1 = __floats2half2_rn(v.z, v.w);
    uint2 u; u.x = *(unsigned*)&h0; u.y = *(unsigned*)&h1;
    *(uint2*)(g_Wh + i) = u;
}

/* ================= LayerNorm: one block per token, half out ================= */
__global__ void ln_kernel(const float* __restrict__ x,
                          const float* __restrict__ gamma,
                          const float* __restrict__ beta) {
    int row = blockIdx.x;
    const float* xr = x + (size_t)row * CH;
    __half*      orow = g_xnh + (size_t)row * CH;
    int t = threadIdx.x;

    float v0 = xr[t], v1 = xr[t + 256], v2 = xr[t + 512];
    float s  = v0 + v1 + v2;
    float sq = v0 * v0 + v1 * v1 + v2 * v2;

    __shared__ float redS[8], redQ[8], stats[2];
    #pragma unroll
    for (int o = 16; o; o >>= 1) {
        s  += __shfl_down_sync(0xffffffffu, s,  o);
        sq += __shfl_down_sync(0xffffffffu, sq, o);
    }
    int w = t >> 5, l = t & 31;
    if (l == 0) { redS[w] = s; redQ[w] = sq; }
    __syncthreads();
    if (t == 0) {
        float S = 0.f, Q = 0.f;
        #pragma unroll
        for (int i = 0; i < 8; i++) { S += redS[i]; Q += redQ[i]; }
        float mu  = S * (1.0f / CH);
        float var = Q * (1.0f / CH) - mu * mu;
        stats[0] = mu;
        stats[1] = rsqrtf(var + LN_EPS);
    }
    __syncthreads();
    float mu = stats[0], rs = stats[1];
    orow[t]       = __float2half_rn((v0 - mu) * rs * gamma[t]       + beta[t]);
    orow[t + 256] = __float2half_rn((v1 - mu) * rs * gamma[t + 256] + beta[t + 256]);
    orow[t + 512] = __float2half_rn((v2 - mu) * rs * gamma[t + 512] + beta[t + 512]);
}

/* ===== fp16 128x128 GEMM compute step (8 warps, warp 32x64) ===== */
#define COMPUTE128H(AS, BS)                                               \
    {                                                                     \
        unsigned a[2][4];                                                 \
        _Pragma("unroll")                                                 \
        for (int mi = 0; mi < 2; mi++) {                                  \
            a[mi][0] = AS[wm + mi*16 + lr    ][lc];                       \
            a[mi][1] = AS[wm + mi*16 + lr + 8][lc];                       \
            a[mi][2] = AS[wm + mi*16 + lr    ][lc + 4];                   \
            a[mi][3] = AS[wm + mi*16 + lr + 8][lc + 4];                   \
        }                                                                 \
        _Pragma("unroll")                                                 \
        for (int ni = 0; ni < 8; ni++) {                                  \
            unsigned b0 = BS[wn + ni*8 + lr][lc];                         \
            unsigned b1 = BS[wn + ni*8 + lr][lc + 4];                     \
            _Pragma("unroll")                                             \
            for (int mi = 0; mi < 2; mi++)                                \
                mma16(acc[mi][ni], a[mi], b0, b1);                        \
        }                                                                 \
    }

#define STAGE_U4(ARR, ROWI, U4OFF, v4)                                    \
    ARR[ROWI][U4OFF + 0] = v4.x; ARR[ROWI][U4OFF + 1] = v4.y;             \
    ARR[ROWI][U4OFF + 2] = v4.z; ARR[ROWI][U4OFF + 3] = v4.w;

/* ========== QKV GEMM (fp16 MMA, 128x128, double-buffered) ========== */
__global__ __launch_bounds__(256) void qkv_gemm(const float* __restrict__ bias) {
    __shared__ unsigned As[2][128][10];
    __shared__ unsigned Bs[2][128][10];
    int m0 = blockIdx.y * 128, n0 = blockIdx.x * 128;
    int t = threadIdx.x;
    int warp = t >> 5, lane = t & 31, lr = lane >> 2, lc = lane & 3;
    int wm = (warp >> 1) * 32, wn = (warp & 1) * 64;
    int sr = t >> 1, so = (t & 1) * 4;
    int sh = (t & 1) * 8;

    const __half* A0 = g_xnh + (size_t)(m0 + sr) * CH + sh;
    const __half* B0 = g_Wh  + (size_t)(n0 + sr) * CH + sh;

    float acc[2][8][4] = {};
    {
        uint4 av = *(const uint4*)A0;
        uint4 bv = *(const uint4*)B0;
        STAGE_U4(As[0], sr, so, av)
        STAGE_U4(Bs[0], sr, so, bv)
    }
    __syncthreads();

    const int NT = CH / 16;
    int buf = 0;
    for (int kt = 0; kt < NT; kt++) {
        uint4 nav, nbv;
        bool nxt = (kt + 1) < NT;
        if (nxt) {
            int k0 = (kt + 1) * 16;
            nav = *(const uint4*)(A0 + k0);
            nbv = *(const uint4*)(B0 + k0);
        }
        COMPUTE128H(As[buf], Bs[buf])
        if (nxt) {
            int nb = buf ^ 1;
            STAGE_U4(As[nb], sr, so, nav)
            STAGE_U4(Bs[nb], sr, so, nbv)
        }
        __syncthreads();
        buf ^= 1;
    }
    #pragma unroll
    for (int mi = 0; mi < 2; mi++)
        #pragma unroll
        for (int ni = 0; ni < 8; ni++) {
            int row = m0 + wm + mi*16 + lr;
            int col = n0 + wn + ni*8 + lc*2;
            float b0 = bias[col], b1 = bias[col + 1];
            __half2 h0 = __floats2half2_rn(acc[mi][ni][0] + b0, acc[mi][ni][1] + b1);
            __half2 h1 = __floats2half2_rn(acc[mi][ni][2] + b0, acc[mi][ni][3] + b1);
            *(unsigned*)(g_qkvh + (size_t)row * QKVC + col)     = *(unsigned*)&h0;
            *(unsigned*)(g_qkvh + (size_t)(row+8) * QKVC + col) = *(unsigned*)&h1;
        }
}

/* ========== Scores (fp16 MMA, 128x128, full-K staged, fp16 S out) ========== */
__global__ __launch_bounds__(256) void score_gemm() {
    int bh = blockIdx.z, b = bh / NH, h = bh % NH;
    const __half* Q = g_qkvh + (size_t)b * SEQ * QKVC + h * HD;
    const __half* K = g_qkvh + (size_t)b * SEQ * QKVC + CH + h * HD;
    __half* S = g_Sh + (size_t)bh * SEQ * SEQ;

    __shared__ unsigned As[4][128][10];
    __shared__ unsigned Bs[4][128][10];
    int m0 = blockIdx.y * 128, n0 = blockIdx.x * 128;
    int t = threadIdx.x;
    int warp = t >> 5, lane = t & 31, lr = lane >> 2, lc = lane & 3;
    int wm = (warp >> 1) * 32, wn = (warp & 1) * 64;
    int sr = t >> 1, so = (t & 1) * 4, sh = (t & 1) * 8;

    const __half* A0 = Q + (size_t)(m0 + sr) * QKVC + sh;
    const __half* B0 = K + (size_t)(n0 + sr) * QKVC + sh;

    #pragma unroll
    for (int kt = 0; kt < 4; kt++) {
        uint4 av = *(const uint4*)(A0 + kt * 16);
        uint4 bv = *(const uint4*)(B0 + kt * 16);
        STAGE_U4(As[kt], sr, so, av)
        STAGE_U4(Bs[kt], sr, so, bv)
    }
    __syncthreads();

    float acc[2][8][4] = {};
    #pragma unroll
    for (int kt = 0; kt < 4; kt++) {
        COMPUTE128H(As[kt], Bs[kt])
    }

    #pragma unroll
    for (int mi = 0; mi < 2; mi++)
        #pragma unroll
        for (int ni = 0; ni < 8; ni++) {
            int row = m0 + wm + mi*16 + lr;
            int col = n0 + wn + ni*8 + lc*2;
            __half2 h0 = __floats2half2_rn(acc[mi][ni][0] * SCALE, acc[mi][ni][1] * SCALE);
            __half2 h1 = __floats2half2_rn(acc[mi][ni][2] * SCALE, acc[mi][ni][3] * SCALE);
            *(unsigned*)(S + (size_t)row * SEQ + col)     = *(unsigned*)&h0;
            *(unsigned*)(S + (size_t)(row+8) * SEQ + col) = *(unsigned*)&h1;
        }
}

/* ============ Lateral inhibition conv + row softmax (fp16 in/out) ============ */
#define CR 4
__global__ __launch_bounds__(256) void conv_softmax_v2() {
    int bh = blockIdx.y;
    int i0 = blockIdx.x * CR;
    const __half* S = g_Sh + (size_t)bh * SEQ * SEQ;
    __half*       P = g_Ph + (size_t)bh * SEQ * SEQ;

    __shared__ float rows[6][SEQ];
    __shared__ float red[CR][8];
    __shared__ float bc[CR];

    int t = threadIdx.x, lane = t & 31, w = t >> 5;
    int j0 = t * 4;

    #pragma unroll
    for (int r = 0; r < 6; r++) {
        int gi = i0 - 1 + r;
        float4 v = make_float4(0.f, 0.f, 0.f, 0.f);
        if (gi >= 0 && gi < SEQ) {
            uint2 u = *(const uint2*)(S + (size_t)gi * SEQ + j0);
            float2 f0 = __half22float2(*(__half2*)&u.x);
            float2 f1 = __half22float2(*(__half2*)&u.y);
            v = make_float4(f0.x, f0.y, f1.x, f1.y);
        }
        *(float4*)&rows[r][j0] = v;
    }
    __syncthreads();

    float a[CR][4], mx[CR];
    #pragma unroll
    for (int r = 0; r < CR; r++) {
        float4 x = *(const float4*)&rows[r    ][j0];
        float4 y = *(const float4*)&rows[r + 1][j0];
        float4 z = *(const float4*)&rows[r + 2][j0];
        float4 vs;
        vs.x = x.x + y.x + z.x;  vs.y = x.y + y.y + z.y;
        vs.z = x.z + y.z + z.z;  vs.w = x.w + y.w + z.w;

        float left  = __shfl_up_sync(0xffffffffu, vs.w, 1);
        float right = __shfl_down_sync(0xffffffffu, vs.x, 1);
        if (lane == 0) {
            int j = j0 - 1;
            left = (j >= 0) ? rows[r][j] + rows[r + 1][j] + rows[r + 2][j] : 0.f;
        }
        if (lane == 31) {
            int j = j0 + 4;
            right = (j < SEQ) ? rows[r][j] + rows[r + 1][j] + rows[r + 2][j] : 0.f;
        }

        a[r][0] = (1.0f + BETA) * y.x - BETA * (left + vs.x + vs.y);
        a[r][1] = (1.0f + BETA) * y.y - BETA * (vs.x + vs.y + vs.z);
        a[r][2] = (1.0f + BETA) * y.z - BETA * (vs.y + vs.z + vs.w);
        a[r][3] = (1.0f + BETA) * y.w - BETA * (vs.z + vs.w + right);
        mx[r] = fmaxf(fmaxf(a[r][0], a[r][1]), fmaxf(a[r][2], a[r][3]));
    }

    #pragma unroll
    for (int r = 0; r < CR; r++) {
        float m = mx[r];
        #pragma unroll
        for (int o = 16; o; o >>= 1) m = fmaxf(m, __shfl_xor_sync(0xffffffffu, m, o));
        if (lane == 0) red[r][w] = m;
    }
    __syncthreads();
    if (t < CR) {
        float m = red[t][0];
        #pragma unroll
        for (int k = 1; k < 8; k++) m = fmaxf(m, red[t][k]);
        bc[t] = m;
    }
    __syncthreads();

    float sm[CR];
    #pragma unroll
    for (int r = 0; r < CR; r++) {
        float M = bc[r];
        float s = 0.f;
        #pragma unroll
        for (int q = 0; q < 4; q++) { a[r][q] = __expf(a[r][q] - M); s += a[r][q]; }
        sm[r] = s;
    }
    __syncthreads();
    #pragma unroll
    for (int r = 0; r < CR; r++) {
        float s = sm[r];
        #pragma unroll
        for (int o = 16; o; o >>= 1) s += __shfl_xor_sync(0xffffffffu, s, o);
        if (lane == 0) red[r][w] = s;
    }
    __syncthreads();
    if (t < CR) {
        float s = 0.f;
        #pragma unroll
        for (int k = 0; k < 8; k++) s += red[t][k];
        bc[t] = 1.0f / s;
    }
    __syncthreads();

    #pragma unroll
    for (int r = 0; r < CR; r++) {
        float inv = bc[r];
        __half2 h01 = __floats2half2_rn(a[r][0] * inv, a[r][1] * inv);
        __half2 h23 = __floats2half2_rn(a[r][2] * inv, a[r][3] * inv);
        uint2 u;
        u.x = *(unsigned*)&h01;
        u.y = *(unsigned*)&h23;
        *(uint2*)(P + (size_t)(i0 + r) * SEQ + j0) = u;
    }
}

/* ========== PV GEMM (fp16 MMA, double-buffered): out = P @ V ========== */
__global__ __launch_bounds__(256) void pv_gemm(float* __restrict__ out) {
    int bh = blockIdx.y, b = bh / NH, h = bh % NH;
    const __half* Pg = g_Ph + (size_t)bh * SEQ * SEQ;
    const __half* Vh = g_qkvh + (size_t)b * SEQ * QKVC + 2 * CH + h * HD;
    int m0 = blockIdx.x * 128;

    __shared__ unsigned Ps[2][128][10];
    __shared__ unsigned Vsu[2][64][10];

    int t = threadIdx.x;
    int warp = t >> 5, lane = t & 31, lr = lane >> 2, lc = lane & 3;
    int wm = (warp >> 1) * 32, wn = (warp & 1) * 32;
    int pr = t >> 1, ph = (t & 1) * 4, phh = (t & 1) * 8;
    int kp = (t & 127) >> 4, n4 = t & 15;

    const __half* Prow = Pg + (size_t)(m0 + pr) * SEQ + phh;

    float acc[2][4][4] = {};

    {
        uint4 pv4 = *(const uint4*)Prow;
        STAGE_U4(Ps[0], pr, ph, pv4)
        if (t < 128) {
            uint2 lo = *(const uint2*)(Vh + (size_t)(2*kp    ) * QKVC + n4 * 4);
            uint2 hi = *(const uint2*)(Vh + (size_t)(2*kp + 1) * QKVC + n4 * 4);
            const __half* lp = (const __half*)&lo;
            const __half* hp = (const __half*)&hi;
            #pragma unroll
            for (int i = 0; i < 4; i++) {
                __half2 pk = __halves2half2(lp[i], hp[i]);
                Vsu[0][n4*4 + i][kp] = *(unsigned*)&pk;
            }
        }
    }
    __syncthreads();

    const int NT = SEQ / 16;
    int buf = 0;
    for (int kt = 0; kt < NT; kt++) {
        uint4 npv; uint2 nlo, nhi;
        bool nxt = (kt + 1) < NT;
        if (nxt) {
            int k0 = (kt + 1) * 16;
            npv = *(const uint4*)(Prow + k0);
            if (t < 128) {
                nlo = *(const uint2*)(Vh + (size_t)(k0 + 2*kp    ) * QKVC + n4 * 4);
                nhi = *(const uint2*)(Vh + (size_t)(k0 + 2*kp + 1) * QKVC + n4 * 4);
            }
        }

        unsigned a[2][4];
        #pragma unroll
        for (int mi = 0; mi < 2; mi++) {
            a[mi][0] = Ps[buf][wm + mi*16 + lr    ][lc];
            a[mi][1] = Ps[buf][wm + mi*16 + lr + 8][lc];
            a[mi][2] = Ps[buf][wm + mi*16 + lr    ][lc + 4];
            a[mi][3] = Ps[buf][wm + mi*16 + lr + 8][lc + 4];
        }
        #pragma unroll
        for (int ni = 0; ni < 4; ni++) {
            unsigned b0 = Vsu[buf][wn + ni*8 + lr][lc];
            unsigned b1 = Vsu[buf][wn + ni*8 + lr][lc + 4];
            #pragma unroll
            for (int mi = 0; mi < 2; mi++)
                mma16(acc[mi][ni], a[mi], b0, b1);
        }

        if (nxt) {
            int nb = buf ^ 1;
            STAGE_U4(Ps[nb], pr, ph, npv)
            if (t < 128) {
                const __half* lp = (const __half*)&nlo;
                const __half* hp = (const __half*)&nhi;
                #pragma unroll
                for (int i = 0; i < 4; i++) {
                    __half2 pk = __halves2half2(lp[i], hp[i]);
                    Vsu[nb][n4*4 + i][kp] = *(unsigned*)&pk;
                }
            }
        }
        __syncthreads();
        buf ^= 1;
    }

    #pragma unroll
    for (int mi = 0; mi < 2; mi++)
        #pragma unroll
        for (int ni = 0; ni < 4; ni++) {
            int row = m0 + wm + mi*16 + lr;
            int col = wn + ni*8 + lc*2;
            out[((size_t)b * SEQ + row) * CH + h*HD + col    ] = acc[mi][ni][0];
            out[((size_t)b * SEQ + row) * CH + h*HD + col + 1] = acc[mi][ni][1];
            out[((size_t)b * SEQ + row + 8) * CH + h*HD + col    ] = acc[mi][ni][2];
            out[((size_t)b * SEQ + row + 8) * CH + h*HD + col + 1] = acc[mi][ni][3];
        }
}

extern "C" void kernel_launch(void* const* d_in, const int* in_sizes, int n_in,
                              void* d_out, int out_size) {
    const float* x     = (const float*)d_in[0];
    const float* qkv_w = (const float*)d_in[1];
    const float* qkv_b = (const float*)d_in[2];
    const float* ln_g  = (const float*)d_in[3];
    const float* ln_b  = (const float*)d_in[4];
    float* out = (float*)d_out;

    wcvt_kernel<<<(QKVC * CH) / (256 * 4), 256>>>(qkv_w);
    ln_kernel<<<ROWS, 256>>>(x, ln_g, ln_b);
    qkv_gemm<<<dim3(QKVC / 128, ROWS / 128), 256>>>(qkv_b);
    score_gemm<<<dim3(SEQ / 128, SEQ / 128, BH), 256>>>();
    conv_softmax_v2<<<dim3(SEQ / CR, BH), 256>>>();
    pv_gemm<<<dim3(SEQ / 128, BH), 256>>>(out);
}

// round 15
// speedup vs baseline: 1.3573x; 1.0911x over previous
#include <cuda_runtime.h>
#include <cuda_fp16.h>
#include <math.h>

#define BN   4
#define SEQ  1024
#define CH   768
#define NH   12
#define HD   64
#define ROWS (BN*SEQ)
#define QKVC (3*CH)
#define BH   (BN*NH)
#define BETA 0.2f
#define SCALE 0.125f
#define LN_EPS 1e-5f

__device__ __half g_xnh[(size_t)ROWS * CH];
__device__ __half g_Wh[(size_t)QKVC * CH];
__device__ __half g_qkvh[(size_t)ROWS * QKVC];
__device__ __half g_Sh[(size_t)BH * SEQ * SEQ];
__device__ __half g_Ph[(size_t)BH * SEQ * SEQ];

__device__ __forceinline__ void mma16(float* c, const unsigned* a,
                                      unsigned b0, unsigned b1) {
    asm volatile(
        "mma.sync.aligned.m16n8k16.row.col.f32.f16.f16.f32 "
        "{%0,%1,%2,%3}, {%4,%5,%6,%7}, {%8,%9}, {%0,%1,%2,%3};"
        : "+f"(c[0]), "+f"(c[1]), "+f"(c[2]), "+f"(c[3])
        : "r"(a[0]), "r"(a[1]), "r"(a[2]), "r"(a[3]), "r"(b0), "r"(b1));
}

/* ================= W -> half ================= */
__global__ void wcvt_kernel(const float* __restrict__ W) {
    int i = (blockIdx.x * 256 + threadIdx.x) * 4;
    float4 v = *(const float4*)(W + i);
    __half2 h0 = __floats2half2_rn(v.x, v.y);
    __half2 h1 = __floats2half2_rn(v.z, v.w);
    uint2 u; u.x = *(unsigned*)&h0; u.y = *(unsigned*)&h1;
    *(uint2*)(g_Wh + i) = u;
}

/* ================= LayerNorm: one block per token, half out ================= */
__global__ void ln_kernel(const float* __restrict__ x,
                          const float* __restrict__ gamma,
                          const float* __restrict__ beta) {
    int row = blockIdx.x;
    const float* xr = x + (size_t)row * CH;
    __half*      orow = g_xnh + (size_t)row * CH;
    int t = threadIdx.x;

    float v0 = xr[t], v1 = xr[t + 256], v2 = xr[t + 512];
    float s  = v0 + v1 + v2;
    float sq = v0 * v0 + v1 * v1 + v2 * v2;

    __shared__ float redS[8], redQ[8], stats[2];
    #pragma unroll
    for (int o = 16; o; o >>= 1) {
        s  += __shfl_down_sync(0xffffffffu, s,  o);
        sq += __shfl_down_sync(0xffffffffu, sq, o);
    }
    int w = t >> 5, l = t & 31;
    if (l == 0) { redS[w] = s; redQ[w] = sq; }
    __syncthreads();
    if (t == 0) {
        float S = 0.f, Q = 0.f;
        #pragma unroll
        for (int i = 0; i < 8; i++) { S += redS[i]; Q += redQ[i]; }
        float mu  = S * (1.0f / CH);
        float var = Q * (1.0f / CH) - mu * mu;
        stats[0] = mu;
        stats[1] = rsqrtf(var + LN_EPS);
    }
    __syncthreads();
    float mu = stats[0], rs = stats[1];
    orow[t]       = __float2half_rn((v0 - mu) * rs * gamma[t]       + beta[t]);
    orow[t + 256] = __float2half_rn((v1 - mu) * rs * gamma[t + 256] + beta[t + 256]);
    orow[t + 512] = __float2half_rn((v2 - mu) * rs * gamma[t + 512] + beta[t + 512]);
}

/* ===== fp16 128x128 GEMM compute step (8 warps, warp 32x64) =====
   smem stride 12 uints: 12*lr+lc covers all 32 banks conflict-free */
#define COMPUTE128H(AS, BS)                                               \
    {                                                                     \
        unsigned a[2][4];                                                 \
        _Pragma("unroll")                                                 \
        for (int mi = 0; mi < 2; mi++) {                                  \
            a[mi][0] = AS[wm + mi*16 + lr    ][lc];                       \
            a[mi][1] = AS[wm + mi*16 + lr + 8][lc];                       \
            a[mi][2] = AS[wm + mi*16 + lr    ][lc + 4];                   \
            a[mi][3] = AS[wm + mi*16 + lr + 8][lc + 4];                   \
        }                                                                 \
        _Pragma("unroll")                                                 \
        for (int ni = 0; ni < 8; ni++) {                                  \
            unsigned b0 = BS[wn + ni*8 + lr][lc];                         \
            unsigned b1 = BS[wn + ni*8 + lr][lc + 4];                     \
            _Pragma("unroll")                                             \
            for (int mi = 0; mi < 2; mi++)                                \
                mma16(acc[mi][ni], a[mi], b0, b1);                        \
        }                                                                 \
    }

#define STAGE_U4(ARR, ROWI, U4OFF, v4)                                    \
    ARR[ROWI][U4OFF + 0] = v4.x; ARR[ROWI][U4OFF + 1] = v4.y;             \
    ARR[ROWI][U4OFF + 2] = v4.z; ARR[ROWI][U4OFF + 3] = v4.w;

/* ========== QKV GEMM (fp16 MMA, 128x128, double-buffered) ========== */
__global__ __launch_bounds__(256) void qkv_gemm(const float* __restrict__ bias) {
    __shared__ unsigned As[2][128][12];
    __shared__ unsigned Bs[2][128][12];
    int m0 = blockIdx.y * 128, n0 = blockIdx.x * 128;
    int t = threadIdx.x;
    int warp = t >> 5, lane = t & 31, lr = lane >> 2, lc = lane & 3;
    int wm = (warp >> 1) * 32, wn = (warp & 1) * 64;
    int sr = t >> 1, so = (t & 1) * 4;
    int sh = (t & 1) * 8;

    const __half* A0 = g_xnh + (size_t)(m0 + sr) * CH + sh;
    const __half* B0 = g_Wh  + (size_t)(n0 + sr) * CH + sh;

    float acc[2][8][4] = {};
    {
        uint4 av = *(const uint4*)A0;
        uint4 bv = *(const uint4*)B0;
        STAGE_U4(As[0], sr, so, av)
        STAGE_U4(Bs[0], sr, so, bv)
    }
    __syncthreads();

    const int NT = CH / 16;
    int buf = 0;
    for (int kt = 0; kt < NT; kt++) {
        uint4 nav, nbv;
        bool nxt = (kt + 1) < NT;
        if (nxt) {
            int k0 = (kt + 1) * 16;
            nav = *(const uint4*)(A0 + k0);
            nbv = *(const uint4*)(B0 + k0);
        }
        COMPUTE128H(As[buf], Bs[buf])
        if (nxt) {
            int nb = buf ^ 1;
            STAGE_U4(As[nb], sr, so, nav)
            STAGE_U4(Bs[nb], sr, so, nbv)
        }
        __syncthreads();
        buf ^= 1;
    }
    #pragma unroll
    for (int mi = 0; mi < 2; mi++)
        #pragma unroll
        for (int ni = 0; ni < 8; ni++) {
            int row = m0 + wm + mi*16 + lr;
            int col = n0 + wn + ni*8 + lc*2;
            float b0 = bias[col], b1 = bias[col + 1];
            __half2 h0 = __floats2half2_rn(acc[mi][ni][0] + b0, acc[mi][ni][1] + b1);
            __half2 h1 = __floats2half2_rn(acc[mi][ni][2] + b0, acc[mi][ni][3] + b1);
            *(unsigned*)(g_qkvh + (size_t)row * QKVC + col)     = *(unsigned*)&h0;
            *(unsigned*)(g_qkvh + (size_t)(row+8) * QKVC + col) = *(unsigned*)&h1;
        }
}

/* ========== Scores (fp16 MMA, 128x128, full-K staged, fp16 S out) ========== */
__global__ __launch_bounds__(256) void score_gemm() {
    int bh = blockIdx.z, b = bh / NH, h = bh % NH;
    const __half* Q = g_qkvh + (size_t)b * SEQ * QKVC + h * HD;
    const __half* K = g_qkvh + (size_t)b * SEQ * QKVC + CH + h * HD;
    __half* S = g_Sh + (size_t)bh * SEQ * SEQ;

    __shared__ unsigned As[4][128][12];
    __shared__ unsigned Bs[4][128][12];
    int m0 = blockIdx.y * 128, n0 = blockIdx.x * 128;
    int t = threadIdx.x;
    int warp = t >> 5, lane = t & 31, lr = lane >> 2, lc = lane & 3;
    int wm = (warp >> 1) * 32, wn = (warp & 1) * 64;
    int sr = t >> 1, so = (t & 1) * 4, sh = (t & 1) * 8;

    const __half* A0 = Q + (size_t)(m0 + sr) * QKVC + sh;
    const __half* B0 = K + (size_t)(n0 + sr) * QKVC + sh;

    #pragma unroll
    for (int kt = 0; kt < 4; kt++) {
        uint4 av = *(const uint4*)(A0 + kt * 16);
        uint4 bv = *(const uint4*)(B0 + kt * 16);
        STAGE_U4(As[kt], sr, so, av)
        STAGE_U4(Bs[kt], sr, so, bv)
    }
    __syncthreads();

    float acc[2][8][4] = {};
    #pragma unroll
    for (int kt = 0; kt < 4; kt++) {
        COMPUTE128H(As[kt], Bs[kt])
    }

    #pragma unroll
    for (int mi = 0; mi < 2; mi++)
        #pragma unroll
        for (int ni = 0; ni < 8; ni++) {
            int row = m0 + wm + mi*16 + lr;
            int col = n0 + wn + ni*8 + lc*2;
            __half2 h0 = __floats2half2_rn(acc[mi][ni][0] * SCALE, acc[mi][ni][1] * SCALE);
            __half2 h1 = __floats2half2_rn(acc[mi][ni][2] * SCALE, acc[mi][ni][3] * SCALE);
            *(unsigned*)(S + (size_t)row * SEQ + col)     = *(unsigned*)&h0;
            *(unsigned*)(S + (size_t)(row+8) * SEQ + col) = *(unsigned*)&h1;
        }
}

/* ============ Lateral inhibition conv + row softmax (fp16 in/out) ============ */
#define CR 4
__global__ __launch_bounds__(256) void conv_softmax_v2() {
    int bh = blockIdx.y;
    int i0 = blockIdx.x * CR;
    const __half* S = g_Sh + (size_t)bh * SEQ * SEQ;
    __half*       P = g_Ph + (size_t)bh * SEQ * SEQ;

    __shared__ float rows[6][SEQ];
    __shared__ float red[CR][8];
    __shared__ float bc[CR];

    int t = threadIdx.x, lane = t & 31, w = t >> 5;
    int j0 = t * 4;

    #pragma unroll
    for (int r = 0; r < 6; r++) {
        int gi = i0 - 1 + r;
        float4 v = make_float4(0.f, 0.f, 0.f, 0.f);
        if (gi >= 0 && gi < SEQ) {
            uint2 u = *(const uint2*)(S + (size_t)gi * SEQ + j0);
            float2 f0 = __half22float2(*(__half2*)&u.x);
            float2 f1 = __half22float2(*(__half2*)&u.y);
            v = make_float4(f0.x, f0.y, f1.x, f1.y);
        }
        *(float4*)&rows[r][j0] = v;
    }
    __syncthreads();

    float a[CR][4], mx[CR];
    #pragma unroll
    for (int r = 0; r < CR; r++) {
        float4 x = *(const float4*)&rows[r    ][j0];
        float4 y = *(const float4*)&rows[r + 1][j0];
        float4 z = *(const float4*)&rows[r + 2][j0];
        float4 vs;
        vs.x = x.x + y.x + z.x;  vs.y = x.y + y.y + z.y;
        vs.z = x.z + y.z + z.z;  vs.w = x.w + y.w + z.w;

        float left  = __shfl_up_sync(0xffffffffu, vs.w, 1);
        float right = __shfl_down_sync(0xffffffffu, vs.x, 1);
        if (lane == 0) {
            int j = j0 - 1;
            left = (j >= 0) ? rows[r][j] + rows[r + 1][j] + rows[r + 2][j] : 0.f;
        }
        if (lane == 31) {
            int j = j0 + 4;
            right = (j < SEQ) ? rows[r][j] + rows[r + 1][j] + rows[r + 2][j] : 0.f;
        }

        a[r][0] = (1.0f + BETA) * y.x - BETA * (left + vs.x + vs.y);
        a[r][1] = (1.0f + BETA) * y.y - BETA * (vs.x + vs.y + vs.z);
        a[r][2] = (1.0f + BETA) * y.z - BETA * (vs.y + vs.z + vs.w);
        a[r][3] = (1.0f + BETA) * y.w - BETA * (vs.z + vs.w + right);
        mx[r] = fmaxf(fmaxf(a[r][0], a[r][1]), fmaxf(a[r][2], a[r][3]));
    }

    #pragma unroll
    for (int r = 0; r < CR; r++) {
        float m = mx[r];
        #pragma unroll
        for (int o = 16; o; o >>= 1) m = fmaxf(m, __shfl_xor_sync(0xffffffffu, m, o));
        if (lane == 0) red[r][w] = m;
    }
    __syncthreads();
    if (t < CR) {
        float m = red[t][0];
        #pragma unroll
        for (int k = 1; k < 8; k++) m = fmaxf(m, red[t][k]);
        bc[t] = m;
    }
    __syncthreads();

    float sm[CR];
    #pragma unroll
    for (int r = 0; r < CR; r++) {
        float M = bc[r];
        float s = 0.f;
        #pragma unroll
        for (int q = 0; q < 4; q++) { a[r][q] = __expf(a[r][q] - M); s += a[r][q]; }
        sm[r] = s;
    }
    __syncthreads();
    #pragma unroll
    for (int r = 0; r < CR; r++) {
        float s = sm[r];
        #pragma unroll
        for (int o = 16; o; o >>= 1) s += __shfl_xor_sync(0xffffffffu, s, o);
        if (lane == 0) red[r][w] = s;
    }
    __syncthreads();
    if (t < CR) {
        float s = 0.f;
        #pragma unroll
        for (int k = 0; k < 8; k++) s += red[t][k];
        bc[t] = 1.0f / s;
    }
    __syncthreads();

    #pragma unroll
    for (int r = 0; r < CR; r++) {
        float inv = bc[r];
        __half2 h01 = __floats2half2_rn(a[r][0] * inv, a[r][1] * inv);
        __half2 h23 = __floats2half2_rn(a[r][2] * inv, a[r][3] * inv);
        uint2 u;
        u.x = *(unsigned*)&h01;
        u.y = *(unsigned*)&h23;
        *(uint2*)(P + (size_t)(i0 + r) * SEQ + j0) = u;
    }
}

/* ========== PV GEMM (fp16 MMA, double-buffered): out = P @ V ========== */
__global__ __launch_bounds__(256) void pv_gemm(float* __restrict__ out) {
    int bh = blockIdx.y, b = bh / NH, h = bh % NH;
    const __half* Pg = g_Ph + (size_t)bh * SEQ * SEQ;
    const __half* Vh = g_qkvh + (size_t)b * SEQ * QKVC + 2 * CH + h * HD;
    int m0 = blockIdx.x * 128;

    __shared__ unsigned Ps[2][128][12];
    __shared__ unsigned Vsu[2][64][12];

    int t = threadIdx.x;
    int warp = t >> 5, lane = t & 31, lr = lane >> 2, lc = lane & 3;
    int wm = (warp >> 1) * 32, wn = (warp & 1) * 32;
    int pr = t >> 1, ph = (t & 1) * 4, phh = (t & 1) * 8;
    int kp = (t & 127) >> 4, n4 = t & 15;

    const __half* Prow = Pg + (size_t)(m0 + pr) * SEQ + phh;

    float acc[2][4][4] = {};

    {
        uint4 pv4 = *(const uint4*)Prow;
        STAGE_U4(Ps[0], pr, ph, pv4)
        if (t < 128) {
            uint2 lo = *(const uint2*)(Vh + (size_t)(2*kp    ) * QKVC + n4 * 4);
            uint2 hi = *(const uint2*)(Vh + (size_t)(2*kp + 1) * QKVC + n4 * 4);
            const __half* lp = (const __half*)&lo;
            const __half* hp = (const __half*)&hi;
            #pragma unroll
            for (int i = 0; i < 4; i++) {
                __half2 pk = __halves2half2(lp[i], hp[i]);
                Vsu[0][n4*4 + i][kp] = *(unsigned*)&pk;
            }
        }
    }
    __syncthreads();

    const int NT = SEQ / 16;
    int buf = 0;
    for (int kt = 0; kt < NT; kt++) {
        uint4 npv; uint2 nlo, nhi;
        bool nxt = (kt + 1) < NT;
        if (nxt) {
            int k0 = (kt + 1) * 16;
            npv = *(const uint4*)(Prow + k0);
            if (t < 128) {
                nlo = *(const uint2*)(Vh + (size_t)(k0 + 2*kp    ) * QKVC + n4 * 4);
                nhi = *(const uint2*)(Vh + (size_t)(k0 + 2*kp + 1) * QKVC + n4 * 4);
            }
        }

        unsigned a[2][4];
        #pragma unroll
        for (int mi = 0; mi < 2; mi++) {
            a[mi][0] = Ps[buf][wm + mi*16 + lr    ][lc];
            a[mi][1] = Ps[buf][wm + mi*16 + lr + 8][lc];
            a[mi][2] = Ps[buf][wm + mi*16 + lr    ][lc + 4];
            a[mi][3] = Ps[buf][wm + mi*16 + lr + 8][lc + 4];
        }
        #pragma unroll
        for (int ni = 0; ni < 4; ni++) {
            unsigned b0 = Vsu[buf][wn + ni*8 + lr][lc];
            unsigned b1 = Vsu[buf][wn + ni*8 + lr][lc + 4];
            #pragma unroll
            for (int mi = 0; mi < 2; mi++)
                mma16(acc[mi][ni], a[mi], b0, b1);
        }

        if (nxt) {
            int nb = buf ^ 1;
            STAGE_U4(Ps[nb], pr, ph, npv)
            if (t < 128) {
                const __half* lp = (const __half*)&nlo;
                const __half* hp = (const __half*)&nhi;
                #pragma unroll
                for (int i = 0; i < 4; i++) {
                    __half2 pk = __halves2half2(lp[i], hp[i]);
                    Vsu[nb][n4*4 + i][kp] = *(unsigned*)&pk;
                }
            }
        }
        __syncthreads();
        buf ^= 1;
    }

    #pragma unroll
    for (int mi = 0; mi < 2; mi++)
        #pragma unroll
        for (int ni = 0; ni < 4; ni++) {
            int row = m0 + wm + mi*16 + lr;
            int col = wn + ni*8 + lc*2;
            out[((size_t)b * SEQ + row) * CH + h*HD + col    ] = acc[mi][ni][0];
            out[((size_t)b * SEQ + row) * CH + h*HD + col + 1] = acc[mi][ni][1];
            out[((size_t)b * SEQ + row + 8) * CH + h*HD + col    ] = acc[mi][ni][2];
            out[((size_t)b * SEQ + row + 8) * CH + h*HD + col + 1] = acc[mi][ni][3];
        }
}

extern "C" void kernel_launch(void* const* d_in, const int* in_sizes, int n_in,
                              void* d_out, int out_size) {
    const float* x     = (const float*)d_in[0];
    const float* qkv_w = (const float*)d_in[1];
    const float* qkv_b = (const float*)d_in[2];
    const float* ln_g  = (const float*)d_in[3];
    const float* ln_b  = (const float*)d_in[4];
    float* out = (float*)d_out;

    wcvt_kernel<<<(QKVC * CH) / (256 * 4), 256>>>(qkv_w);
    ln_kernel<<<ROWS, 256>>>(x, ln_g, ln_b);
    qkv_gemm<<<dim3(QKVC / 128, ROWS / 128), 256>>>(qkv_b);
    score_gemm<<<dim3(SEQ / 128, SEQ / 128, BH), 256>>>();
    conv_softmax_v2<<<dim3(SEQ / CR, BH), 256>>>();
    pv_gemm<<<dim3(SEQ / 128, BH), 256>>>(out);
}

// round 16
// speedup vs baseline: 1.3868x; 1.0218x over previous
#include <cuda_runtime.h>
#include <cuda_fp16.h>
#include <math.h>

#define BN   4
#define SEQ  1024
#define CH   768
#define NH   12
#define HD   64
#define ROWS (BN*SEQ)
#define QKVC (3*CH)
#define BH   (BN*NH)
#define BETA 0.2f
#define SCALE 0.125f
#define LN_EPS 1e-5f

__device__ __half g_xnh[(size_t)ROWS * CH];
__device__ __half g_Wh[(size_t)QKVC * CH];
__device__ __half g_qkvh[(size_t)ROWS * QKVC];
__device__ __half g_Sh[(size_t)BH * SEQ * SEQ];
__device__ __half g_Ph[(size_t)BH * SEQ * SEQ];

__device__ __forceinline__ void mma16(float* c, const unsigned* a,
                                      unsigned b0, unsigned b1) {
    asm volatile(
        "mma.sync.aligned.m16n8k16.row.col.f32.f16.f16.f32 "
        "{%0,%1,%2,%3}, {%4,%5,%6,%7}, {%8,%9}, {%0,%1,%2,%3};"
        : "+f"(c[0]), "+f"(c[1]), "+f"(c[2]), "+f"(c[3])
        : "r"(a[0]), "r"(a[1]), "r"(a[2]), "r"(a[3]), "r"(b0), "r"(b1));
}
__device__ __forceinline__ unsigned sm_addr(const void* p) {
    return (unsigned)__cvta_generic_to_shared(p);
}
__device__ __forceinline__ void ldsm4(unsigned* r, unsigned addr) {
    asm volatile("ldmatrix.sync.aligned.m8n8.x4.shared.b16 {%0,%1,%2,%3}, [%4];"
        : "=r"(r[0]), "=r"(r[1]), "=r"(r[2]), "=r"(r[3]) : "r"(addr));
}

/* ================= W -> half ================= */
__global__ void wcvt_kernel(const float* __restrict__ W) {
    int i = (blockIdx.x * 256 + threadIdx.x) * 4;
    float4 v = *(const float4*)(W + i);
    __half2 h0 = __floats2half2_rn(v.x, v.y);
    __half2 h1 = __floats2half2_rn(v.z, v.w);
    uint2 u; u.x = *(unsigned*)&h0; u.y = *(unsigned*)&h1;
    *(uint2*)(g_Wh + i) = u;
}

/* ================= LayerNorm: one block per token, half out ================= */
__global__ void ln_kernel(const float* __restrict__ x,
                          const float* __restrict__ gamma,
                          const float* __restrict__ beta) {
    int row = blockIdx.x;
    const float* xr = x + (size_t)row * CH;
    __half*      orow = g_xnh + (size_t)row * CH;
    int t = threadIdx.x;

    float v0 = xr[t], v1 = xr[t + 256], v2 = xr[t + 512];
    float s  = v0 + v1 + v2;
    float sq = v0 * v0 + v1 * v1 + v2 * v2;

    __shared__ float redS[8], redQ[8], stats[2];
    #pragma unroll
    for (int o = 16; o; o >>= 1) {
        s  += __shfl_down_sync(0xffffffffu, s,  o);
        sq += __shfl_down_sync(0xffffffffu, sq, o);
    }
    int w = t >> 5, l = t & 31;
    if (l == 0) { redS[w] = s; redQ[w] = sq; }
    __syncthreads();
    if (t == 0) {
        float S = 0.f, Q = 0.f;
        #pragma unroll
        for (int i = 0; i < 8; i++) { S += redS[i]; Q += redQ[i]; }
        float mu  = S * (1.0f / CH);
        float var = Q * (1.0f / CH) - mu * mu;
        stats[0] = mu;
        stats[1] = rsqrtf(var + LN_EPS);
    }
    __syncthreads();
    float mu = stats[0], rs = stats[1];
    orow[t]       = __float2half_rn((v0 - mu) * rs * gamma[t]       + beta[t]);
    orow[t + 256] = __float2half_rn((v1 - mu) * rs * gamma[t + 256] + beta[t + 256]);
    orow[t + 512] = __float2half_rn((v2 - mu) * rs * gamma[t + 512] + beta[t + 512]);
}

/* ===== fp16 128x128 GEMM compute step via ldmatrix (8 warps, warp 32x64) =====
   a_row/a_col, b_row/b_col are per-lane ldmatrix source coordinates.       */
#define COMPUTE128H(AS, BS)                                               \
    {                                                                     \
        unsigned a[2][4];                                                 \
        _Pragma("unroll")                                                 \
        for (int mi = 0; mi < 2; mi++)                                    \
            ldsm4(a[mi], sm_addr(&AS[wm + mi*16 + a_row][a_col]));        \
        _Pragma("unroll")                                                 \
        for (int pi = 0; pi < 4; pi++) {                                  \
            unsigned bq[4];                                               \
            ldsm4(bq, sm_addr(&BS[wn + pi*16 + b_row][b_col]));           \
            _Pragma("unroll")                                             \
            for (int mi = 0; mi < 2; mi++) {                              \
                mma16(acc[mi][2*pi    ], a[mi], bq[0], bq[1]);            \
                mma16(acc[mi][2*pi + 1], a[mi], bq[2], bq[3]);            \
            }                                                             \
        }                                                                 \
    }

#define LDSM_COORDS                                                       \
    int a_row = lane & 15;                                                \
    int a_col = (lane >> 4) * 4;                                          \
    int b_row = (lane & 7) + ((lane >> 4) << 3);                          \
    int b_col = ((lane >> 3) & 1) * 4;

#define STAGE_U4(ARR, ROWI, U4OFF, v4)                                    \
    ARR[ROWI][U4OFF + 0] = v4.x; ARR[ROWI][U4OFF + 1] = v4.y;             \
    ARR[ROWI][U4OFF + 2] = v4.z; ARR[ROWI][U4OFF + 3] = v4.w;

/* ========== QKV GEMM (fp16 MMA + ldmatrix, 128x128, double-buffered) ========== */
__global__ __launch_bounds__(256) void qkv_gemm(const float* __restrict__ bias) {
    __shared__ unsigned As[2][128][12];
    __shared__ unsigned Bs[2][128][12];
    int m0 = blockIdx.y * 128, n0 = blockIdx.x * 128;
    int t = threadIdx.x;
    int warp = t >> 5, lane = t & 31, lr = lane >> 2, lc = lane & 3;
    int wm = (warp >> 1) * 32, wn = (warp & 1) * 64;
    LDSM_COORDS
    int sr = t >> 1, so = (t & 1) * 4;
    int sh = (t & 1) * 8;

    const __half* A0 = g_xnh + (size_t)(m0 + sr) * CH + sh;
    const __half* B0 = g_Wh  + (size_t)(n0 + sr) * CH + sh;

    float acc[2][8][4] = {};
    {
        uint4 av = *(const uint4*)A0;
        uint4 bv = *(const uint4*)B0;
        STAGE_U4(As[0], sr, so, av)
        STAGE_U4(Bs[0], sr, so, bv)
    }
    __syncthreads();

    const int NT = CH / 16;
    int buf = 0;
    for (int kt = 0; kt < NT; kt++) {
        uint4 nav, nbv;
        bool nxt = (kt + 1) < NT;
        if (nxt) {
            int k0 = (kt + 1) * 16;
            nav = *(const uint4*)(A0 + k0);
            nbv = *(const uint4*)(B0 + k0);
        }
        COMPUTE128H(As[buf], Bs[buf])
        if (nxt) {
            int nb = buf ^ 1;
            STAGE_U4(As[nb], sr, so, nav)
            STAGE_U4(Bs[nb], sr, so, nbv)
        }
        __syncthreads();
        buf ^= 1;
    }
    #pragma unroll
    for (int mi = 0; mi < 2; mi++)
        #pragma unroll
        for (int ni = 0; ni < 8; ni++) {
            int row = m0 + wm + mi*16 + lr;
            int col = n0 + wn + ni*8 + lc*2;
            float b0 = bias[col], b1 = bias[col + 1];
            __half2 h0 = __floats2half2_rn(acc[mi][ni][0] + b0, acc[mi][ni][1] + b1);
            __half2 h1 = __floats2half2_rn(acc[mi][ni][2] + b0, acc[mi][ni][3] + b1);
            *(unsigned*)(g_qkvh + (size_t)row * QKVC + col)     = *(unsigned*)&h0;
            *(unsigned*)(g_qkvh + (size_t)(row+8) * QKVC + col) = *(unsigned*)&h1;
        }
}

/* ========== Scores (fp16 MMA + ldmatrix, 128x128, full-K staged) ========== */
__global__ __launch_bounds__(256) void score_gemm() {
    int bh = blockIdx.z, b = bh / NH, h = bh % NH;
    const __half* Q = g_qkvh + (size_t)b * SEQ * QKVC + h * HD;
    const __half* K = g_qkvh + (size_t)b * SEQ * QKVC + CH + h * HD;
    __half* S = g_Sh + (size_t)bh * SEQ * SEQ;

    __shared__ unsigned As[4][128][12];
    __shared__ unsigned Bs[4][128][12];
    int m0 = blockIdx.y * 128, n0 = blockIdx.x * 128;
    int t = threadIdx.x;
    int warp = t >> 5, lane = t & 31, lr = lane >> 2, lc = lane & 3;
    int wm = (warp >> 1) * 32, wn = (warp & 1) * 64;
    LDSM_COORDS
    int sr = t >> 1, so = (t & 1) * 4, sh = (t & 1) * 8;

    const __half* A0 = Q + (size_t)(m0 + sr) * QKVC + sh;
    const __half* B0 = K + (size_t)(n0 + sr) * QKVC + sh;

    #pragma unroll
    for (int kt = 0; kt < 4; kt++) {
        uint4 av = *(const uint4*)(A0 + kt * 16);
        uint4 bv = *(const uint4*)(B0 + kt * 16);
        STAGE_U4(As[kt], sr, so, av)
        STAGE_U4(Bs[kt], sr, so, bv)
    }
    __syncthreads();

    float acc[2][8][4] = {};
    #pragma unroll
    for (int kt = 0; kt < 4; kt++) {
        COMPUTE128H(As[kt], Bs[kt])
    }

    #pragma unroll
    for (int mi = 0; mi < 2; mi++)
        #pragma unroll
        for (int ni = 0; ni < 8; ni++) {
            int row = m0 + wm + mi*16 + lr;
            int col = n0 + wn + ni*8 + lc*2;
            __half2 h0 = __floats2half2_rn(acc[mi][ni][0] * SCALE, acc[mi][ni][1] * SCALE);
            __half2 h1 = __floats2half2_rn(acc[mi][ni][2] * SCALE, acc[mi][ni][3] * SCALE);
            *(unsigned*)(S + (size_t)row * SEQ + col)     = *(unsigned*)&h0;
            *(unsigned*)(S + (size_t)(row+8) * SEQ + col) = *(unsigned*)&h1;
        }
}

/* ============ Lateral inhibition conv + row softmax (fp16 in/out) ============ */
#define CR 4
__global__ __launch_bounds__(256) void conv_softmax_v2() {
    int bh = blockIdx.y;
    int i0 = blockIdx.x * CR;
    const __half* S = g_Sh + (size_t)bh * SEQ * SEQ;
    __half*       P = g_Ph + (size_t)bh * SEQ * SEQ;

    __shared__ float rows[6][SEQ];
    __shared__ float red[CR][8];
    __shared__ float bc[CR];

    int t = threadIdx.x, lane = t & 31, w = t >> 5;
    int j0 = t * 4;

    #pragma unroll
    for (int r = 0; r < 6; r++) {
        int gi = i0 - 1 + r;
        float4 v = make_float4(0.f, 0.f, 0.f, 0.f);
        if (gi >= 0 && gi < SEQ) {
            uint2 u = *(const uint2*)(S + (size_t)gi * SEQ + j0);
            float2 f0 = __half22float2(*(__half2*)&u.x);
            float2 f1 = __half22float2(*(__half2*)&u.y);
            v = make_float4(f0.x, f0.y, f1.x, f1.y);
        }
        *(float4*)&rows[r][j0] = v;
    }
    __syncthreads();

    float a[CR][4], mx[CR];
    #pragma unroll
    for (int r = 0; r < CR; r++) {
        float4 x = *(const float4*)&rows[r    ][j0];
        float4 y = *(const float4*)&rows[r + 1][j0];
        float4 z = *(const float4*)&rows[r + 2][j0];
        float4 vs;
        vs.x = x.x + y.x + z.x;  vs.y = x.y + y.y + z.y;
        vs.z = x.z + y.z + z.z;  vs.w = x.w + y.w + z.w;

        float left  = __shfl_up_sync(0xffffffffu, vs.w, 1);
        float right = __shfl_down_sync(0xffffffffu, vs.x, 1);
        if (lane == 0) {
            int j = j0 - 1;
            left = (j >= 0) ? rows[r][j] + rows[r + 1][j] + rows[r + 2][j] : 0.f;
        }
        if (lane == 31) {
            int j = j0 + 4;
            right = (j < SEQ) ? rows[r][j] + rows[r + 1][j] + rows[r + 2][j] : 0.f;
        }

        a[r][0] = (1.0f + BETA) * y.x - BETA * (left + vs.x + vs.y);
        a[r][1] = (1.0f + BETA) * y.y - BETA * (vs.x + vs.y + vs.z);
        a[r][2] = (1.0f + BETA) * y.z - BETA * (vs.y + vs.z + vs.w);
        a[r][3] = (1.0f + BETA) * y.w - BETA * (vs.z + vs.w + right);
        mx[r] = fmaxf(fmaxf(a[r][0], a[r][1]), fmaxf(a[r][2], a[r][3]));
    }

    #pragma unroll
    for (int r = 0; r < CR; r++) {
        float m = mx[r];
        #pragma unroll
        for (int o = 16; o; o >>= 1) m = fmaxf(m, __shfl_xor_sync(0xffffffffu, m, o));
        if (lane == 0) red[r][w] = m;
    }
    __syncthreads();
    if (t < CR) {
        float m = red[t][0];
        #pragma unroll
        for (int k = 1; k < 8; k++) m = fmaxf(m, red[t][k]);
        bc[t] = m;
    }
    __syncthreads();

    float sm[CR];
    #pragma unroll
    for (int r = 0; r < CR; r++) {
        float M = bc[r];
        float s = 0.f;
        #pragma unroll
        for (int q = 0; q < 4; q++) { a[r][q] = __expf(a[r][q] - M); s += a[r][q]; }
        sm[r] = s;
    }
    __syncthreads();
    #pragma unroll
    for (int r = 0; r < CR; r++) {
        float s = sm[r];
        #pragma unroll
        for (int o = 16; o; o >>= 1) s += __shfl_xor_sync(0xffffffffu, s, o);
        if (lane == 0) red[r][w] = s;
    }
    __syncthreads();
    if (t < CR) {
        float s = 0.f;
        #pragma unroll
        for (int k = 0; k < 8; k++) s += red[t][k];
        bc[t] = 1.0f / s;
    }
    __syncthreads();

    #pragma unroll
    for (int r = 0; r < CR; r++) {
        float inv = bc[r];
        __half2 h01 = __floats2half2_rn(a[r][0] * inv, a[r][1] * inv);
        __half2 h23 = __floats2half2_rn(a[r][2] * inv, a[r][3] * inv);
        uint2 u;
        u.x = *(unsigned*)&h01;
        u.y = *(unsigned*)&h23;
        *(uint2*)(P + (size_t)(i0 + r) * SEQ + j0) = u;
    }
}

/* ========== PV GEMM (fp16 MMA + ldmatrix, double-buffered) ========== */
__global__ __launch_bounds__(256) void pv_gemm(float* __restrict__ out) {
    int bh = blockIdx.y, b = bh / NH, h = bh % NH;
    const __half* Pg = g_Ph + (size_t)bh * SEQ * SEQ;
    const __half* Vh = g_qkvh + (size_t)b * SEQ * QKVC + 2 * CH + h * HD;
    int m0 = blockIdx.x * 128;

    __shared__ unsigned Ps[2][128][12];
    __shared__ unsigned Vsu[2][64][12];

    int t = threadIdx.x;
    int warp = t >> 5, lane = t & 31, lr = lane >> 2, lc = lane & 3;
    int wm = (warp >> 1) * 32, wn = (warp & 1) * 32;
    LDSM_COORDS
    int pr = t >> 1, ph = (t & 1) * 4, phh = (t & 1) * 8;
    int kp = (t & 127) >> 4, n4 = t & 15;

    const __half* Prow = Pg + (size_t)(m0 + pr) * SEQ + phh;

    float acc[2][4][4] = {};

    {
        uint4 pv4 = *(const uint4*)Prow;
        STAGE_U4(Ps[0], pr, ph, pv4)
        if (t < 128) {
            uint2 lo = *(const uint2*)(Vh + (size_t)(2*kp    ) * QKVC + n4 * 4);
            uint2 hi = *(const uint2*)(Vh + (size_t)(2*kp + 1) * QKVC + n4 * 4);
            const __half* lp = (const __half*)&lo;
            const __half* hp = (const __half*)&hi;
            #pragma unroll
            for (int i = 0; i < 4; i++) {
                __half2 pk = __halves2half2(lp[i], hp[i]);
                Vsu[0][n4*4 + i][kp] = *(unsigned*)&pk;
            }
        }
    }
    __syncthreads();

    const int NT = SEQ / 16;
    int buf = 0;
    for (int kt = 0; kt < NT; kt++) {
        uint4 npv; uint2 nlo, nhi;
        bool nxt = (kt + 1) < NT;
        if (nxt) {
            int k0 = (kt + 1) * 16;
            npv = *(const uint4*)(Prow + k0);
            if (t < 128) {
                nlo = *(const uint2*)(Vh + (size_t)(k0 + 2*kp    ) * QKVC + n4 * 4);
                nhi = *(const uint2*)(Vh + (size_t)(k0 + 2*kp + 1) * QKVC + n4 * 4);
            }
        }

        unsigned a[2][4];
        #pragma unroll
        for (int mi = 0; mi < 2; mi++)
            ldsm4(a[mi], sm_addr(&Ps[buf][wm + mi*16 + a_row][a_col]));
        #pragma unroll
        for (int pi = 0; pi < 2; pi++) {
            unsigned bq[4];
            ldsm4(bq, sm_addr(&Vsu[buf][wn + pi*16 + b_row][b_col]));
            #pragma unroll
            for (int mi = 0; mi < 2; mi++) {
                mma16(acc[mi][2*pi    ], a[mi], bq[0], bq[1]);
                mma16(acc[mi][2*pi + 1], a[mi], bq[2], bq[3]);
            }
        }

        if (nxt) {
            int nb = buf ^ 1;
            STAGE_U4(Ps[nb], pr, ph, npv)
            if (t < 128) {
                const __half* lp = (const __half*)&nlo;
                const __half* hp = (const __half*)&nhi;
                #pragma unroll
                for (int i = 0; i < 4; i++) {
                    __half2 pk = __halves2half2(lp[i], hp[i]);
                    Vsu[nb][n4*4 + i][kp] = *(unsigned*)&pk;
                }
            }
        }
        __syncthreads();
        buf ^= 1;
    }

    #pragma unroll
    for (int mi = 0; mi < 2; mi++)
        #pragma unroll
        for (int ni = 0; ni < 4; ni++) {
            int row = m0 + wm + mi*16 + lr;
            int col = wn + ni*8 + lc*2;
            out[((size_t)b * SEQ + row) * CH + h*HD + col    ] = acc[mi][ni][0];
            out[((size_t)b * SEQ + row) * CH + h*HD + col + 1] = acc[mi][ni][1];
            out[((size_t)b * SEQ + row + 8) * CH + h*HD + col    ] = acc[mi][ni][2];
            out[((size_t)b * SEQ + row + 8) * CH + h*HD + col + 1] = acc[mi][ni][3];
        }
}

extern "C" void kernel_launch(void* const* d_in, const int* in_sizes, int n_in,
                              void* d_out, int out_size) {
    const float* x     = (const float*)d_in[0];
    const float* qkv_w = (const float*)d_in[1];
    const float* qkv_b = (const float*)d_in[2];
    const float* ln_g  = (const float*)d_in[3];
    const float* ln_b  = (const float*)d_in[4];
    float* out = (float*)d_out;

    wcvt_kernel<<<(QKVC * CH) / (256 * 4), 256>>>(qkv_w);
    ln_kernel<<<ROWS, 256>>>(x, ln_g, ln_b);
    qkv_gemm<<<dim3(QKVC / 128, ROWS / 128), 256>>>(qkv_b);
    score_gemm<<<dim3(SEQ / 128, SEQ / 128, BH), 256>>>();
    conv_softmax_v2<<<dim3(SEQ / CR, BH), 256>>>();
    pv_gemm<<<dim3(SEQ / 128, BH), 256>>>(out);
}

// round 17
// speedup vs baseline: 1.4065x; 1.0142x over previous
#include <cuda_runtime.h>
#include <cuda_fp16.h>
#include <math.h>

#define BN   4
#define SEQ  1024
#define CH   768
#define NH   12
#define HD   64
#define ROWS (BN*SEQ)
#define QKVC (3*CH)
#define BH   (BN*NH)
#define BETA 0.2f
#define SCALE 0.125f
#define LN_EPS 1e-5f

__device__ __half g_xnh[(size_t)ROWS * CH];
__device__ __half g_Wh[(size_t)QKVC * CH];
__device__ __half g_qkvh[(size_t)ROWS * QKVC];
__device__ __half g_Sh[(size_t)BH * SEQ * SEQ];
__device__ __half g_Ph[(size_t)BH * SEQ * SEQ];

__device__ __forceinline__ void mma16(float* c, const unsigned* a,
                                      unsigned b0, unsigned b1) {
    asm volatile(
        "mma.sync.aligned.m16n8k16.row.col.f32.f16.f16.f32 "
        "{%0,%1,%2,%3}, {%4,%5,%6,%7}, {%8,%9}, {%0,%1,%2,%3};"
        : "+f"(c[0]), "+f"(c[1]), "+f"(c[2]), "+f"(c[3])
        : "r"(a[0]), "r"(a[1]), "r"(a[2]), "r"(a[3]), "r"(b0), "r"(b1));
}
__device__ __forceinline__ unsigned sm_addr(const void* p) {
    return (unsigned)__cvta_generic_to_shared(p);
}
__device__ __forceinline__ void ldsm4(unsigned* r, unsigned addr) {
    asm volatile("ldmatrix.sync.aligned.m8n8.x4.shared.b16 {%0,%1,%2,%3}, [%4];"
        : "=r"(r[0]), "=r"(r[1]), "=r"(r[2]), "=r"(r[3]) : "r"(addr));
}

/* ================= W -> half ================= */
__global__ void wcvt_kernel(const float* __restrict__ W) {
    int i = (blockIdx.x * 256 + threadIdx.x) * 4;
    float4 v = *(const float4*)(W + i);
    __half2 h0 = __floats2half2_rn(v.x, v.y);
    __half2 h1 = __floats2half2_rn(v.z, v.w);
    uint2 u; u.x = *(unsigned*)&h0; u.y = *(unsigned*)&h1;
    *(uint2*)(g_Wh + i) = u;
}

/* ================= LayerNorm: one block per token, half out ================= */
__global__ void ln_kernel(const float* __restrict__ x,
                          const float* __restrict__ gamma,
                          const float* __restrict__ beta) {
    int row = blockIdx.x;
    const float* xr = x + (size_t)row * CH;
    __half*      orow = g_xnh + (size_t)row * CH;
    int t = threadIdx.x;

    float v0 = xr[t], v1 = xr[t + 256], v2 = xr[t + 512];
    float s  = v0 + v1 + v2;
    float sq = v0 * v0 + v1 * v1 + v2 * v2;

    __shared__ float redS[8], redQ[8], stats[2];
    #pragma unroll
    for (int o = 16; o; o >>= 1) {
        s  += __shfl_down_sync(0xffffffffu, s,  o);
        sq += __shfl_down_sync(0xffffffffu, sq, o);
    }
    int w = t >> 5, l = t & 31;
    if (l == 0) { redS[w] = s; redQ[w] = sq; }
    __syncthreads();
    if (t == 0) {
        float S = 0.f, Q = 0.f;
        #pragma unroll
        for (int i = 0; i < 8; i++) { S += redS[i]; Q += redQ[i]; }
        float mu  = S * (1.0f / CH);
        float var = Q * (1.0f / CH) - mu * mu;
        stats[0] = mu;
        stats[1] = rsqrtf(var + LN_EPS);
    }
    __syncthreads();
    float mu = stats[0], rs = stats[1];
    orow[t]       = __float2half_rn((v0 - mu) * rs * gamma[t]       + beta[t]);
    orow[t + 256] = __float2half_rn((v1 - mu) * rs * gamma[t + 256] + beta[t + 256]);
    orow[t + 512] = __float2half_rn((v2 - mu) * rs * gamma[t + 512] + beta[t + 512]);
}

/* ===== fp16 128x128 GEMM compute step via ldmatrix (8 warps, warp 32x64) ===== */
#define COMPUTE128H(AS, BS)                                               \
    {                                                                     \
        unsigned a[2][4];                                                 \
        _Pragma("unroll")                                                 \
        for (int mi = 0; mi < 2; mi++)                                    \
            ldsm4(a[mi], sm_addr(&AS[wm + mi*16 + a_row][a_col]));        \
        _Pragma("unroll")                                                 \
        for (int pi = 0; pi < 4; pi++) {                                  \
            unsigned bq[4];                                               \
            ldsm4(bq, sm_addr(&BS[wn + pi*16 + b_row][b_col]));           \
            _Pragma("unroll")                                             \
            for (int mi = 0; mi < 2; mi++) {                              \
                mma16(acc[mi][2*pi    ], a[mi], bq[0], bq[1]);            \
                mma16(acc[mi][2*pi + 1], a[mi], bq[2], bq[3]);            \
            }                                                             \
        }                                                                 \
    }

#define LDSM_COORDS                                                       \
    int a_row = lane & 15;                                                \
    int a_col = (lane >> 4) * 4;                                          \
    int b_row = (lane & 7) + ((lane >> 4) << 3);                          \
    int b_col = ((lane >> 3) & 1) * 4;

#define STAGE_U4(ARR, ROWI, U4OFF, v4)                                    \
    ARR[ROWI][U4OFF + 0] = v4.x; ARR[ROWI][U4OFF + 1] = v4.y;             \
    ARR[ROWI][U4OFF + 2] = v4.z; ARR[ROWI][U4OFF + 3] = v4.w;

/* ========== QKV GEMM (fp16 MMA + ldmatrix, 128x128, double-buffered) ========== */
__global__ __launch_bounds__(256) void qkv_gemm(const float* __restrict__ bias) {
    __shared__ unsigned As[2][128][12];
    __shared__ unsigned Bs[2][128][12];
    int m0 = blockIdx.y * 128, n0 = blockIdx.x * 128;
    int t = threadIdx.x;
    int warp = t >> 5, lane = t & 31, lr = lane >> 2, lc = lane & 3;
    int wm = (warp >> 1) * 32, wn = (warp & 1) * 64;
    LDSM_COORDS
    int sr = t >> 1, so = (t & 1) * 4;
    int sh = (t & 1) * 8;

    const __half* A0 = g_xnh + (size_t)(m0 + sr) * CH + sh;
    const __half* B0 = g_Wh  + (size_t)(n0 + sr) * CH + sh;

    float acc[2][8][4] = {};
    {
        uint4 av = *(const uint4*)A0;
        uint4 bv = *(const uint4*)B0;
        STAGE_U4(As[0], sr, so, av)
        STAGE_U4(Bs[0], sr, so, bv)
    }
    __syncthreads();

    const int NT = CH / 16;
    int buf = 0;
    for (int kt = 0; kt < NT; kt++) {
        uint4 nav, nbv;
        bool nxt = (kt + 1) < NT;
        if (nxt) {
            int k0 = (kt + 1) * 16;
            nav = *(const uint4*)(A0 + k0);
            nbv = *(const uint4*)(B0 + k0);
        }
        COMPUTE128H(As[buf], Bs[buf])
        if (nxt) {
            int nb = buf ^ 1;
            STAGE_U4(As[nb], sr, so, nav)
            STAGE_U4(Bs[nb], sr, so, nbv)
        }
        __syncthreads();
        buf ^= 1;
    }
    #pragma unroll
    for (int mi = 0; mi < 2; mi++)
        #pragma unroll
        for (int ni = 0; ni < 8; ni++) {
            int row = m0 + wm + mi*16 + lr;
            int col = n0 + wn + ni*8 + lc*2;
            float b0 = bias[col], b1 = bias[col + 1];
            __half2 h0 = __floats2half2_rn(acc[mi][ni][0] + b0, acc[mi][ni][1] + b1);
            __half2 h1 = __floats2half2_rn(acc[mi][ni][2] + b0, acc[mi][ni][3] + b1);
            *(unsigned*)(g_qkvh + (size_t)row * QKVC + col)     = *(unsigned*)&h0;
            *(unsigned*)(g_qkvh + (size_t)(row+8) * QKVC + col) = *(unsigned*)&h1;
        }
}

/* ========== Scores v3: Q-resident CTA, 4 n-tiles, K double-buffered ==========
   grid (2, 8, BH); smem: Qs[4][128][12] + Ks[2][4][128][12] (dynamic, 72KB) */
#define SC_SMEM ((4*128*12 + 2*4*128*12) * 4)

__global__ __launch_bounds__(256) void score_gemm() {
    extern __shared__ unsigned ssm[];
    typedef unsigned Tile[128][12];
    Tile* Qs = (Tile*)ssm;                    /* 4 k-tiles  */
    Tile* Ks = (Tile*)(ssm + 4*128*12);       /* 2 bufs x 4 k-tiles */

    int bh = blockIdx.z, b = bh / NH, h = bh % NH;
    int m0 = blockIdx.y * 128;
    int nh0 = blockIdx.x * 4;                 /* first n-tile index */
    const __half* Q = g_qkvh + (size_t)b * SEQ * QKVC + h * HD;
    const __half* K = g_qkvh + (size_t)b * SEQ * QKVC + CH + h * HD;
    __half* S = g_Sh + (size_t)bh * SEQ * SEQ;

    int t = threadIdx.x;
    int warp = t >> 5, lane = t & 31, lr = lane >> 2, lc = lane & 3;
    int wm = (warp >> 1) * 32, wn = (warp & 1) * 64;
    LDSM_COORDS
    int sr = t >> 1, so = (t & 1) * 4, sh = (t & 1) * 8;

    const __half* A0 = Q + (size_t)(m0 + sr) * QKVC + sh;

    /* stage Q (4 k-tiles) + first K tile */
    {
        const __half* B0 = K + (size_t)(nh0 * 128 + sr) * QKVC + sh;
        #pragma unroll
        for (int kt = 0; kt < 4; kt++) {
            uint4 av = *(const uint4*)(A0 + kt * 16);
            uint4 bv = *(const uint4*)(B0 + kt * 16);
            STAGE_U4(Qs[kt], sr, so, av)
            STAGE_U4(Ks[kt], sr, so, bv)
        }
    }
    __syncthreads();

    int buf = 0;
    for (int ns = 0; ns < 4; ns++) {
        /* prefetch next K tile into registers */
        uint4 nb0, nb1, nb2, nb3;
        bool nxt = (ns + 1) < 4;
        if (nxt) {
            const __half* B0 = K + (size_t)((nh0 + ns + 1) * 128 + sr) * QKVC + sh;
            nb0 = *(const uint4*)(B0);
            nb1 = *(const uint4*)(B0 + 16);
            nb2 = *(const uint4*)(B0 + 32);
            nb3 = *(const uint4*)(B0 + 48);
        }

        float acc[2][8][4] = {};
        #pragma unroll
        for (int kt = 0; kt < 4; kt++) {
            COMPUTE128H(Qs[kt], Ks[buf * 4 + kt])
        }

        /* write S tile */
        int n0 = (nh0 + ns) * 128;
        #pragma unroll
        for (int mi = 0; mi < 2; mi++)
            #pragma unroll
            for (int ni = 0; ni < 8; ni++) {
                int row = m0 + wm + mi*16 + lr;
                int col = n0 + wn + ni*8 + lc*2;
                __half2 h0 = __floats2half2_rn(acc[mi][ni][0] * SCALE, acc[mi][ni][1] * SCALE);
                __half2 h1 = __floats2half2_rn(acc[mi][ni][2] * SCALE, acc[mi][ni][3] * SCALE);
                *(unsigned*)(S + (size_t)row * SEQ + col)     = *(unsigned*)&h0;
                *(unsigned*)(S + (size_t)(row+8) * SEQ + col) = *(unsigned*)&h1;
            }

        if (nxt) {
            int nb = (buf ^ 1) * 4;
            STAGE_U4(Ks[nb + 0], sr, so, nb0)
            STAGE_U4(Ks[nb + 1], sr, so, nb1)
            STAGE_U4(Ks[nb + 2], sr, so, nb2)
            STAGE_U4(Ks[nb + 3], sr, so, nb3)
            __syncthreads();
        }
        buf ^= 1;
    }
}

/* ============ Lateral inhibition conv + row softmax (fp16 in/out) ============ */
#define CR 4
__global__ __launch_bounds__(256) void conv_softmax_v2() {
    int bh = blockIdx.y;
    int i0 = blockIdx.x * CR;
    const __half* S = g_Sh + (size_t)bh * SEQ * SEQ;
    __half*       P = g_Ph + (size_t)bh * SEQ * SEQ;

    __shared__ float rows[6][SEQ];
    __shared__ float red[CR][8];
    __shared__ float bc[CR];

    int t = threadIdx.x, lane = t & 31, w = t >> 5;
    int j0 = t * 4;

    #pragma unroll
    for (int r = 0; r < 6; r++) {
        int gi = i0 - 1 + r;
        float4 v = make_float4(0.f, 0.f, 0.f, 0.f);
        if (gi >= 0 && gi < SEQ) {
            uint2 u = *(const uint2*)(S + (size_t)gi * SEQ + j0);
            float2 f0 = __half22float2(*(__half2*)&u.x);
            float2 f1 = __half22float2(*(__half2*)&u.y);
            v = make_float4(f0.x, f0.y, f1.x, f1.y);
        }
        *(float4*)&rows[r][j0] = v;
    }
    __syncthreads();

    float a[CR][4], mx[CR];
    #pragma unroll
    for (int r = 0; r < CR; r++) {
        float4 x = *(const float4*)&rows[r    ][j0];
        float4 y = *(const float4*)&rows[r + 1][j0];
        float4 z = *(const float4*)&rows[r + 2][j0];
        float4 vs;
        vs.x = x.x + y.x + z.x;  vs.y = x.y + y.y + z.y;
        vs.z = x.z + y.z + z.z;  vs.w = x.w + y.w + z.w;

        float left  = __shfl_up_sync(0xffffffffu, vs.w, 1);
        float right = __shfl_down_sync(0xffffffffu, vs.x, 1);
        if (lane == 0) {
            int j = j0 - 1;
            left = (j >= 0) ? rows[r][j] + rows[r + 1][j] + rows[r + 2][j] : 0.f;
        }
        if (lane == 31) {
            int j = j0 + 4;
            right = (j < SEQ) ? rows[r][j] + rows[r + 1][j] + rows[r + 2][j] : 0.f;
        }

        a[r][0] = (1.0f + BETA) * y.x - BETA * (left + vs.x + vs.y);
        a[r][1] = (1.0f + BETA) * y.y - BETA * (vs.x + vs.y + vs.z);
        a[r][2] = (1.0f + BETA) * y.z - BETA * (vs.y + vs.z + vs.w);
        a[r][3] = (1.0f + BETA) * y.w - BETA * (vs.z + vs.w + right);
        mx[r] = fmaxf(fmaxf(a[r][0], a[r][1]), fmaxf(a[r][2], a[r][3]));
    }

    #pragma unroll
    for (int r = 0; r < CR; r++) {
        float m = mx[r];
        #pragma unroll
        for (int o = 16; o; o >>= 1) m = fmaxf(m, __shfl_xor_sync(0xffffffffu, m, o));
        if (lane == 0) red[r][w] = m;
    }
    __syncthreads();
    if (t < CR) {
        float m = red[t][0];
        #pragma unroll
        for (int k = 1; k < 8; k++) m = fmaxf(m, red[t][k]);
        bc[t] = m;
    }
    __syncthreads();

    float sm[CR];
    #pragma unroll
    for (int r = 0; r < CR; r++) {
        float M = bc[r];
        float s = 0.f;
        #pragma unroll
        for (int q = 0; q < 4; q++) { a[r][q] = __expf(a[r][q] - M); s += a[r][q]; }
        sm[r] = s;
    }
    __syncthreads();
    #pragma unroll
    for (int r = 0; r < CR; r++) {
        float s = sm[r];
        #pragma unroll
        for (int o = 16; o; o >>= 1) s += __shfl_xor_sync(0xffffffffu, s, o);
        if (lane == 0) red[r][w] = s;
    }
    __syncthreads();
    if (t < CR) {
        float s = 0.f;
        #pragma unroll
        for (int k = 0; k < 8; k++) s += red[t][k];
        bc[t] = 1.0f / s;
    }
    __syncthreads();

    #pragma unroll
    for (int r = 0; r < CR; r++) {
        float inv = bc[r];
        __half2 h01 = __floats2half2_rn(a[r][0] * inv, a[r][1] * inv);
        __half2 h23 = __floats2half2_rn(a[r][2] * inv, a[r][3] * inv);
        uint2 u;
        u.x = *(unsigned*)&h01;
        u.y = *(unsigned*)&h23;
        *(uint2*)(P + (size_t)(i0 + r) * SEQ + j0) = u;
    }
}

/* ========== PV GEMM (fp16 MMA + ldmatrix, double-buffered) ========== */
__global__ __launch_bounds__(256) void pv_gemm(float* __restrict__ out) {
    int bh = blockIdx.y, b = bh / NH, h = bh % NH;
    const __half* Pg = g_Ph + (size_t)bh * SEQ * SEQ;
    const __half* Vh = g_qkvh + (size_t)b * SEQ * QKVC + 2 * CH + h * HD;
    int m0 = blockIdx.x * 128;

    __shared__ unsigned Ps[2][128][12];
    __shared__ unsigned Vsu[2][64][12];

    int t = threadIdx.x;
    int warp = t >> 5, lane = t & 31, lr = lane >> 2, lc = lane & 3;
    int wm = (warp >> 1) * 32, wn = (warp & 1) * 32;
    LDSM_COORDS
    int pr = t >> 1, ph = (t & 1) * 4, phh = (t & 1) * 8;
    int kp = (t & 127) >> 4, n4 = t & 15;

    const __half* Prow = Pg + (size_t)(m0 + pr) * SEQ + phh;

    float acc[2][4][4] = {};

    {
        uint4 pv4 = *(const uint4*)Prow;
        STAGE_U4(Ps[0], pr, ph, pv4)
        if (t < 128) {
            uint2 lo = *(const uint2*)(Vh + (size_t)(2*kp    ) * QKVC + n4 * 4);
            uint2 hi = *(const uint2*)(Vh + (size_t)(2*kp + 1) * QKVC + n4 * 4);
            const __half* lp = (const __half*)&lo;
            const __half* hp = (const __half*)&hi;
            #pragma unroll
            for (int i = 0; i < 4; i++) {
                __half2 pk = __halves2half2(lp[i], hp[i]);
                Vsu[0][n4*4 + i][kp] = *(unsigned*)&pk;
            }
        }
    }
    __syncthreads();

    const int NT = SEQ / 16;
    int buf = 0;
    for (int kt = 0; kt < NT; kt++) {
        uint4 npv; uint2 nlo, nhi;
        bool nxt = (kt + 1) < NT;
        if (nxt) {
            int k0 = (kt + 1) * 16;
            npv = *(const uint4*)(Prow + k0);
            if (t < 128) {
                nlo = *(const uint2*)(Vh + (size_t)(k0 + 2*kp    ) * QKVC + n4 * 4);
                nhi = *(const uint2*)(Vh + (size_t)(k0 + 2*kp + 1) * QKVC + n4 * 4);
            }
        }

        unsigned a[2][4];
        #pragma unroll
        for (int mi = 0; mi < 2; mi++)
            ldsm4(a[mi], sm_addr(&Ps[buf][wm + mi*16 + a_row][a_col]));
        #pragma unroll
        for (int pi = 0; pi < 2; pi++) {
            unsigned bq[4];
            ldsm4(bq, sm_addr(&Vsu[buf][wn + pi*16 + b_row][b_col]));
            #pragma unroll
            for (int mi = 0; mi < 2; mi++) {
                mma16(acc[mi][2*pi    ], a[mi], bq[0], bq[1]);
                mma16(acc[mi][2*pi + 1], a[mi], bq[2], bq[3]);
            }
        }

        if (nxt) {
            int nb = buf ^ 1;
            STAGE_U4(Ps[nb], pr, ph, npv)
            if (t < 128) {
                const __half* lp = (const __half*)&nlo;
                const __half* hp = (const __half*)&nhi;
                #pragma unroll
                for (int i = 0; i < 4; i++) {
                    __half2 pk = __halves2half2(lp[i], hp[i]);
                    Vsu[nb][n4*4 + i][kp] = *(unsigned*)&pk;
                }
            }
        }
        __syncthreads();
        buf ^= 1;
    }

    #pragma unroll
    for (int mi = 0; mi < 2; mi++)
        #pragma unroll
        for (int ni = 0; ni < 4; ni++) {
            int row = m0 + wm + mi*16 + lr;
            int col = wn + ni*8 + lc*2;
            out[((size_t)b * SEQ + row) * CH + h*HD + col    ] = acc[mi][ni][0];
            out[((size_t)b * SEQ + row) * CH + h*HD + col + 1] = acc[mi][ni][1];
            out[((size_t)b * SEQ + row + 8) * CH + h*HD + col    ] = acc[mi][ni][2];
            out[((size_t)b * SEQ + row + 8) * CH + h*HD + col + 1] = acc[mi][ni][3];
        }
}

extern "C" void kernel_launch(void* const* d_in, const int* in_sizes, int n_in,
                              void* d_out, int out_size) {
    const float* x     = (const float*)d_in[0];
    const float* qkv_w = (const float*)d_in[1];
    const float* qkv_b = (const float*)d_in[2];
    const float* ln_g  = (const float*)d_in[3];
    const float* ln_b  = (const float*)d_in[4];
    float* out = (float*)d_out;

    cudaFuncSetAttribute(score_gemm, cudaFuncAttributeMaxDynamicSharedMemorySize,
                         SC_SMEM);

    wcvt_kernel<<<(QKVC * CH) / (256 * 4), 256>>>(qkv_w);
    ln_kernel<<<ROWS, 256>>>(x, ln_g, ln_b);
    qkv_gemm<<<dim3(QKVC / 128, ROWS / 128), 256>>>(qkv_b);
    score_gemm<<<dim3(2, SEQ / 128, BH), 256, SC_SMEM>>>();
    conv_softmax_v2<<<dim3(SEQ / CR, BH), 256>>>();
    pv_gemm<<<dim3(SEQ / 128, BH), 256>>>(out);
}